// round 9
// baseline (speedup 1.0000x reference)
#include <cuda_runtime.h>
#include <cstdint>

// Problem constants
#define BB   4
#define SS   1024
#define DIN  768
#define HH   12
#define DH   64
#define WWRD (HH*DIN*DH)     // words per weight matrix

// Scratch (device globals; no allocs allowed).
// g_Xr: x pre-rounded to tf32 grid, pair-unit layout:
//   flat chunk i = (row*24 + kc); word w in [0,32): u=w>>1, hf=w&1,
//   value = x[row][kc*32 + (u>>2)*8 + (u&3) + hf*4]
// g_Wr: W^T pre-rounded, pair-unit: [(m*12+h)*24+kc][n][32 words], same w mapping over k.
__device__ __align__(16) uint32_t g_Xr[BB*SS*DIN];
__device__ __align__(16) uint32_t g_Wr[3*WWRD];
__device__ __align__(16) float    g_Qf[BB*HH*SS*DH];          // Q fp32 [b,h,s,e]
__device__ __align__(16) uint32_t g_Kf[(size_t)BB*HH*SS*DH];  // K tf32 frag units
__device__ __align__(16) uint32_t g_Vf[(size_t)BB*HH*DH*SS];  // V tf32 frag units

// ---------------------------------------------------------------------------
// helpers
// ---------------------------------------------------------------------------
__device__ __forceinline__ uint32_t f2tf32(float f) {
    uint32_t r;
    asm("cvt.rna.tf32.f32 %0, %1;" : "=r"(r) : "f"(f));
    return r;
}

__device__ __forceinline__ void mma_tf32(float c[4],
                                         uint32_t a0, uint32_t a1, uint32_t a2, uint32_t a3,
                                         uint32_t b0, uint32_t b1) {
    asm volatile(
        "mma.sync.aligned.m16n8k8.row.col.f32.tf32.tf32.f32 "
        "{%0,%1,%2,%3}, {%4,%5,%6,%7}, {%8,%9}, {%0,%1,%2,%3};"
        : "+f"(c[0]), "+f"(c[1]), "+f"(c[2]), "+f"(c[3])
        : "r"(a0), "r"(a1), "r"(a2), "r"(a3), "r"(b0), "r"(b1));
}

__device__ __forceinline__ void cpa16(uint32_t smem_addr, const void* gptr) {
    asm volatile("cp.async.cg.shared.global [%0], [%1], 16;"
                 :: "r"(smem_addr), "l"(gptr));
}
__device__ __forceinline__ void cpa_commit() {
    asm volatile("cp.async.commit_group;");
}
template <int N>
__device__ __forceinline__ void cpa_wait() {
    asm volatile("cp.async.wait_group %0;" :: "n"(N));
}

// ---------------------------------------------------------------------------
// Kernel 0a: round x to the tf32 grid (bits+0x1000; HW mma truncates -> rna)
// AND permute each 32-col chunk into pair-unit order. One chunk per thread.
// ---------------------------------------------------------------------------
__global__ __launch_bounds__(256)
void prep_x(const float* __restrict__ x) {
    const int i = blockIdx.x*256 + threadIdx.x;   // chunk 0..98303
    uint32_t in[32];
    #pragma unroll
    for (int q = 0; q < 8; q++)
        *(uint4*)&in[q*4] = ((const uint4*)x)[i*8 + q];
    uint32_t outw[32];
    #pragma unroll
    for (int w = 0; w < 32; w++) {
        int u = w >> 1, hf = w & 1;
        int c = (u >> 2)*8 + (u & 3) + hf*4;
        outw[w] = in[c] + 0x1000u;
    }
    #pragma unroll
    for (int q = 0; q < 8; q++)
        ((uint4*)g_Xr)[i*8 + q] = *(uint4*)&outw[q*4];
}

// ---------------------------------------------------------------------------
// Kernel 0b: round + transpose-permute W into [(m,h,kc)][n][32] pair-units.
// grid (24 kc, 12 h, 3 m), 256 threads, smem bounce for coalescing.
// ---------------------------------------------------------------------------
__global__ __launch_bounds__(256)
void prep_w(const float* __restrict__ Wq, const float* __restrict__ Wk,
            const float* __restrict__ Wv) {
    __shared__ uint32_t sm[32*65];
    const int kc = blockIdx.x, h = blockIdx.y, m = blockIdx.z;
    const int tid = threadIdx.x;
    const float* src = ((m == 0) ? Wq : (m == 1) ? Wk : Wv)
                       + (size_t)h*DIN*DH + (size_t)kc*32*DH;
    #pragma unroll
    for (int it = 0; it < 8; it++) {
        int idx = tid + it*256;            // 0..2047
        int k = idx >> 6, n = idx & 63;
        sm[k*65 + n] = __float_as_uint(src[k*64 + n]);
    }
    __syncthreads();
    uint32_t* dst = g_Wr + ((size_t)((m*HH + h)*24 + kc))*2048;
    #pragma unroll
    for (int it = 0; it < 8; it++) {
        int idx = tid + it*256;            // 0..2047
        int n = idx >> 5, w = idx & 31;
        int u = w >> 1, hf = w & 1;
        int c = (u >> 2)*8 + (u & 3) + hf*4;
        dst[idx] = sm[c*65 + n] + 0x1000u;
    }
}

// ---------------------------------------------------------------------------
// Kernel 1: fused QKV projection, cp.async tf32 GEMM, pair-unit smem, wide LDS.
// grid (4096/128, 12); 512 threads (16 warps: 4m x 4n). 3-stage pipeline,
// ONE barrier per k-chunk. Block: M=128, N=64 x3 mats. Warp: m32 x n16 x3.
// ---------------------------------------------------------------------------
#define PAW  4096                // words: A part of a stage (128 rows x 32)
#define PSTG (PAW + 3*64*32)     // 10240 words per stage (40KB)
#define PNC  (DIN/32)            // 24 k-chunks

__global__ __launch_bounds__(512, 1)
void qkv_proj_kernel() {
    extern __shared__ uint32_t psm[];

    const int tid = threadIdx.x;
    const int wid = tid >> 5, lane = tid & 31;
    const int tg = lane >> 2, tig = lane & 3;
    const int wm = wid >> 2, wn = wid & 3;
    const int h = blockIdx.y;
    const int rowblk = blockIdx.x * 128;

    const uint32_t smem_base = (uint32_t)__cvta_generic_to_shared(psm);

    float acc[3][2][2][4];
    #pragma unroll
    for (int m = 0; m < 3; m++)
        #pragma unroll
        for (int i = 0; i < 2; i++)
            #pragma unroll
            for (int j = 0; j < 2; j++)
                #pragma unroll
                for (int r = 0; r < 4; r++) acc[m][i][j][r] = 0.f;

    auto copy_chunk = [&](int kc, int stage) {
        const uint32_t sb = smem_base + stage * (PSTG*4);
        // A: 1024 16B chunks (128 rows x 8), chunk-swizzled by row
        #pragma unroll
        for (int u = 0; u < 2; u++) {
            int idx = tid + u*512, r = idx >> 3, cc = idx & 7;
            int ccs = cc ^ (r & 7);
            cpa16(sb + (r*32 + ccs*4)*4,
                  g_Xr + ((size_t)(rowblk + r)*24 + kc)*32 + cc*4);
        }
        // B: 1536 16B chunks (3 mats x 64 n x 8), swizzled by n
        #pragma unroll
        for (int u = 0; u < 3; u++) {
            int idx = tid + u*512;
            int m = idx >> 9, rem = idx & 511;
            int n = rem >> 3, cc = rem & 7;
            int ccs = cc ^ (n & 7);
            cpa16(sb + (PAW + m*2048 + n*32 + ccs*4)*4,
                  g_Wr + ((size_t)((m*HH + h)*24 + kc))*2048 + n*32 + cc*4);
        }
        cpa_commit();
    };

    copy_chunk(0, 0);
    copy_chunk(1, 1);

    for (int kc = 0; kc < PNC; kc++) {
        if (kc == PNC-1) cpa_wait<0>(); else cpa_wait<1>();
        __syncthreads();                    // all warps done with stage (kc-1)%3
        if (kc + 2 < PNC) copy_chunk(kc + 2, (kc + 2) % 3);

        const uint32_t* Sa = psm + (kc % 3) * PSTG;
        const uint32_t* Sb = Sa + PAW;

        #pragma unroll
        for (int kk = 0; kk < 4; kk++) {
            const int u = kk*4 + tig;
            const int cc = u >> 1, sub = u & 1;
            uint32_t a[2][4];
            #pragma unroll
            for (int ms = 0; ms < 2; ms++) {
                int r0 = wm*32 + ms*16 + tg;           // r0&7 == tg
                uint2 w0 = *(const uint2*)&Sa[r0*32       + (cc ^ tg)*4 + sub*2];
                uint2 w1 = *(const uint2*)&Sa[(r0 + 8)*32 + (cc ^ tg)*4 + sub*2];
                a[ms][0] = w0.x; a[ms][1] = w1.x; a[ms][2] = w0.y; a[ms][3] = w1.y;
            }
            #pragma unroll
            for (int m = 0; m < 3; m++) {
                #pragma unroll
                for (int j = 0; j < 2; j++) {
                    int n0 = wn*16 + j*8 + tg;         // n0&7 == tg
                    uint2 bw = *(const uint2*)&Sb[m*2048 + n0*32 + (cc ^ tg)*4 + sub*2];
                    #pragma unroll
                    for (int ms = 0; ms < 2; ms++)
                        mma_tf32(acc[m][ms][j], a[ms][0], a[ms][1], a[ms][2], a[ms][3],
                                 bw.x, bw.y);
                }
            }
        }
    }
    __syncthreads();   // all warps finished mma before smem reuse below

    // ------------------- Epilogue -------------------
    const int b = rowblk >> 10;
    const int s0 = rowblk & 1023;
    const size_t base = (((size_t)b*HH + h)*SS);

    // Q: fp32 direct
    #pragma unroll
    for (int ms = 0; ms < 2; ms++) {
        int r0 = s0 + wm*32 + ms*16 + tg;
        #pragma unroll
        for (int j = 0; j < 2; j++) {
            int c0 = wn*16 + j*8 + tig*2;
            #pragma unroll
            for (int half = 0; half < 2; half++) {
                *(float2*)&g_Qf[(base + r0 + half*8)*DH + c0] =
                    make_float2(acc[0][ms][j][half*2], acc[0][ms][j][half*2+1]);
            }
        }
    }

    // K, V: bounce through smem (fp32, stride 68), emit unit layouts linearly.
    float* Ksm = (float*)psm;                 // [128][68]
    float* Vsm = (float*)psm + 128*68;        // [128][68]
    #pragma unroll
    for (int ms = 0; ms < 2; ms++) {
        int rl = wm*32 + ms*16 + tg;
        #pragma unroll
        for (int j = 0; j < 2; j++) {
            int c0 = wn*16 + j*8 + tig*2;
            #pragma unroll
            for (int half = 0; half < 2; half++) {
                *(float2*)&Ksm[(rl + half*8)*68 + c0] =
                    make_float2(acc[1][ms][j][half*2], acc[1][ms][j][half*2+1]);
                *(float2*)&Vsm[(rl + half*8)*68 + c0] =
                    make_float2(acc[2][ms][j][half*2], acc[2][ms][j][half*2+1]);
            }
        }
    }
    __syncthreads();

    // Kf: 4096 8B units {k(c), k(c+4)} (c = k8*8+tgu), linear stores
    {
        uint32_t* kf = g_Kf + (base + s0)*DH;
        #pragma unroll
        for (int u = 0; u < 8; u++) {
            int idx = tid + u*512;            // 0..4095
            int sl = idx >> 5, un = idx & 31;
            int k8 = un >> 2, tgu = un & 3;
            int c = k8*8 + tgu;
            float f0 = Ksm[sl*68 + c];
            float f1 = Ksm[sl*68 + c + 4];
            *(uint2*)&kf[(size_t)sl*64 + un*2] = make_uint2(f2tf32(f0), f2tf32(f1));
        }
    }
    // Vf: 4096 8B units {v(s), v(s+4)}
    {
        uint32_t* vf = g_Vf + ((size_t)b*HH + h) * (DH*SS);
        #pragma unroll
        for (int u = 0; u < 8; u++) {
            int idx = tid + u*512;            // 0..4095
            int e = idx >> 6, rem = idx & 63;
            int ks8l = rem >> 2, tgu = rem & 3;
            int sl = ks8l*8 + tgu;
            float f0 = Vsm[(sl    )*68 + e];
            float f1 = Vsm[(sl + 4)*68 + e];
            *(uint2*)&vf[(size_t)e*1024 + ((s0 >> 3) + ks8l)*8 + tgu*2] =
                make_uint2(f2tf32(f0), f2tf32(f1));
        }
    }
}

// ---------------------------------------------------------------------------
// Kernel 2: tensor-core causal flash attention (R7-proven; Q pre-scaled).
// grid (16, 12, 4); 128 threads; cp.async 2-stage; 2 CTAs/SM.
// ---------------------------------------------------------------------------
#define STW 8192     // words per stage: K 4096 + V 4096

__global__ __launch_bounds__(128, 2)
void attn_kernel(float* __restrict__ out) {
    extern __shared__ uint32_t smu[];

    const int mt = gridDim.x - 1 - blockIdx.x;
    const int h = blockIdx.y, b = blockIdx.z;
    const int tid = threadIdx.x, wid = tid >> 5, lane = tid & 31;
    const int tg = lane >> 2, tig = lane & 3;
    const int m0 = mt * 64;
    const size_t bh = ((size_t)b*HH + h) * SS;
    const float*    gqf = g_Qf + bh*DH;
    const uint32_t* gkf = g_Kf + bh*DH;
    const uint32_t* gvf = g_Vf + ((size_t)b*HH + h) * (DH*SS);

    const uint32_t smem_base = (uint32_t)__cvta_generic_to_shared(smu);

    // Q fragments: pre-scaled by 0.125 (exact), split big/small tf32
    uint32_t qb[8][4], qs[8][4];
    {
        const int r0 = m0 + wid*16 + tg;
        #pragma unroll
        for (int k = 0; k < 8; k++) {
            float f[4];
            f[0] = 0.125f * gqf[(size_t)(r0    )*DH + k*8 + tig    ];
            f[1] = 0.125f * gqf[(size_t)(r0 + 8)*DH + k*8 + tig    ];
            f[2] = 0.125f * gqf[(size_t)(r0    )*DH + k*8 + tig + 4];
            f[3] = 0.125f * gqf[(size_t)(r0 + 8)*DH + k*8 + tig + 4];
            #pragma unroll
            for (int i = 0; i < 4; i++) {
                qb[k][i] = f2tf32(f[i]);
                qs[k][i] = f2tf32(f[i] - __uint_as_float(qb[k][i]));
            }
        }
    }

    auto copy_tile = [&](int kt, int stage) {
        const uint32_t sb = smem_base + stage * (STW*4);
        #pragma unroll
        for (int u = 0; u < 8; u++) {
            int idx = tid + u*128;
            int s = idx >> 4, cc = idx & 15;
            int ccs = cc ^ ((s & 7) << 1);
            cpa16(sb + s*256 + ccs*16,
                  gkf + ((size_t)(kt*64 + s)*64 + cc*4));
        }
        #pragma unroll
        for (int u = 0; u < 8; u++) {
            int idx = tid + u*128;
            int e = idx >> 4, p = idx & 15;
            int un = 2*p;
            int usw = un ^ ((e & 7) << 2);
            cpa16(sb + 4096*4 + (e*32 + usw)*8,
                  gvf + (size_t)e*1024 + (kt*32 + un)*2);
        }
        cpa_commit();
    };

    float o[8][4];
    #pragma unroll
    for (int j = 0; j < 8; j++)
        #pragma unroll
        for (int i = 0; i < 4; i++) o[j][i] = 0.f;
    float mrow[2] = {-1e30f, -1e30f};
    float lrow[2] = {0.f, 0.f};

    copy_tile(0, 0);

    for (int kt = 0; kt <= mt; kt++) {
        if (kt < mt) { copy_tile(kt+1, (kt+1)&1); cpa_wait<1>(); }
        else         { cpa_wait<0>(); }
        __syncthreads();

        const uint32_t* Kst = smu + (kt&1)*STW;
        const uint32_t* Vst = Kst + 4096;

        float c[8][4];
        #pragma unroll
        for (int j = 0; j < 8; j++)
            #pragma unroll
            for (int i = 0; i < 4; i++) c[j][i] = 0.f;

        #pragma unroll
        for (int k = 0; k < 8; k++) {
            const int un = k*4 + tig;
            const int cc = un >> 1, half = un & 1;
            #pragma unroll
            for (int j = 0; j < 8; j++) {
                const int nr = j*8 + tg;
                int ccs = cc ^ ((nr & 7) << 1);
                uint2 kv = *(const uint2*)&Kst[nr*64 + ccs*4 + half*2];
                mma_tf32(c[j], qb[k][0], qb[k][1], qb[k][2], qb[k][3], kv.x, kv.y);
                mma_tf32(c[j], qs[k][0], qs[k][1], qs[k][2], qs[k][3], kv.x, kv.y);
            }
        }

        if (kt == mt) {       // diagonal tile: causal mask
            const int rl0 = wid*16 + tg, rl1 = rl0 + 8;
            #pragma unroll
            for (int j = 0; j < 8; j++) {
                int c0 = j*8 + 2*tig, c1 = c0 + 1;
                if (c0 > rl0) c[j][0] = -1e30f;
                if (c1 > rl0) c[j][1] = -1e30f;
                if (c0 > rl1) c[j][2] = -1e30f;
                if (c1 > rl1) c[j][3] = -1e30f;
            }
        }

        float alpha[2];
        #pragma unroll
        for (int h2 = 0; h2 < 2; h2++) {
            float mx = -1e30f;
            #pragma unroll
            for (int j = 0; j < 8; j++) {
                mx = fmaxf(mx, c[j][h2*2]);
                mx = fmaxf(mx, c[j][h2*2 + 1]);
            }
            mx = fmaxf(mx, __shfl_xor_sync(0xffffffffu, mx, 1));
            mx = fmaxf(mx, __shfl_xor_sync(0xffffffffu, mx, 2));
            float mnew = fmaxf(mrow[h2], mx);
            float sum = 0.f;
            #pragma unroll
            for (int j = 0; j < 8; j++) {
                float p0 = __expf(c[j][h2*2]     - mnew);
                float p1 = __expf(c[j][h2*2 + 1] - mnew);
                c[j][h2*2]     = p0;
                c[j][h2*2 + 1] = p1;
                sum += p0 + p1;
            }
            sum += __shfl_xor_sync(0xffffffffu, sum, 1);
            sum += __shfl_xor_sync(0xffffffffu, sum, 2);
            alpha[h2] = __expf(mrow[h2] - mnew);
            mrow[h2] = mnew;
            lrow[h2] = lrow[h2]*alpha[h2] + sum;
        }

        #pragma unroll
        for (int j = 0; j < 8; j++) {
            o[j][0] *= alpha[0]; o[j][1] *= alpha[0];
            o[j][2] *= alpha[1]; o[j][3] *= alpha[1];
        }

        const int src0 = (tg << 2) + (tig >> 1);
        const int src1 = src0 + 2;
        const bool odd = (tig & 1);
        #pragma unroll
        for (int k = 0; k < 8; k++) {
            float e0 = __shfl_sync(0xffffffffu, c[k][0], src0);
            float o0 = __shfl_sync(0xffffffffu, c[k][1], src0);
            float e1 = __shfl_sync(0xffffffffu, c[k][2], src0);
            float o1 = __shfl_sync(0xffffffffu, c[k][3], src0);
            float e2 = __shfl_sync(0xffffffffu, c[k][0], src1);
            float o2 = __shfl_sync(0xffffffffu, c[k][1], src1);
            float e3 = __shfl_sync(0xffffffffu, c[k][2], src1);
            float o3 = __shfl_sync(0xffffffffu, c[k][3], src1);
            uint32_t a0 = f2tf32(odd ? o0 : e0);
            uint32_t a1 = f2tf32(odd ? o1 : e1);
            uint32_t a2 = f2tf32(odd ? o2 : e2);
            uint32_t a3 = f2tf32(odd ? o3 : e3);

            const int usw = (k*4 + tig) ^ (tg << 2);
            #pragma unroll
            for (int jn = 0; jn < 8; jn++) {
                const int e = jn*8 + tg;
                uint2 vf = *(const uint2*)&Vst[(e*32 + usw)*2];
                mma_tf32(o[jn], a0, a1, a2, a3, vf.x, vf.y);
            }
        }
        __syncthreads();
    }

    const float inv0 = 1.f / lrow[0], inv1 = 1.f / lrow[1];
    const int r0 = m0 + wid*16 + tg;
    #pragma unroll
    for (int j = 0; j < 8; j++) {
        int col = h*DH + j*8 + 2*tig;
        *(float2*)&out[((size_t)b*SS + r0    )*(HH*DH) + col] =
            make_float2(o[j][0]*inv0, o[j][1]*inv0);
        *(float2*)&out[((size_t)b*SS + r0 + 8)*(HH*DH) + col] =
            make_float2(o[j][2]*inv1, o[j][3]*inv1);
    }
}

// ---------------------------------------------------------------------------
extern "C" void kernel_launch(void* const* d_in, const int* in_sizes, int n_in,
                              void* d_out, int out_size) {
    const float* x  = (const float*)d_in[0];
    const float* Wq = (const float*)d_in[1];
    const float* Wk = (const float*)d_in[2];
    const float* Wv = (const float*)d_in[3];
    float* out = (float*)d_out;

    prep_x<<<(BB*SS*DIN/32)/256, 256>>>(x);              // 384 blocks
    prep_w<<<dim3(24, HH, 3), 256>>>(Wq, Wk, Wv);

    const int proj_smem = 3 * PSTG * (int)sizeof(uint32_t);        // 122,880 B
    cudaFuncSetAttribute(qkv_proj_kernel, cudaFuncAttributeMaxDynamicSharedMemorySize,
                         proj_smem);
    qkv_proj_kernel<<<dim3((BB*SS)/128, HH), 512, proj_smem>>>();

    const int attn_smem = 2 * STW * (int)sizeof(uint32_t);         // 65,536 B
    cudaFuncSetAttribute(attn_kernel, cudaFuncAttributeMaxDynamicSharedMemorySize,
                         attn_smem);
    attn_kernel<<<dim3(SS/64, HH, BB), 128, attn_smem>>>(out);
}

// round 10
// speedup vs baseline: 1.0812x; 1.0812x over previous
#include <cuda_runtime.h>
#include <cstdint>

// Problem constants
#define BB   4
#define SS   1024
#define DIN  768
#define HH   12
#define DH   64
#define WWRD (HH*DIN*DH)     // words per weight matrix (589824)

// Scratch (device globals; no allocs allowed).
__device__ __align__(16) uint32_t g_Xr[BB*SS*DIN];      // x pre-rounded to tf32 grid
__device__ __align__(16) uint32_t g_Wr[3*WWRD];         // Wq|Wk|Wv pre-rounded
__device__ __align__(16) float    g_Qf[BB*HH*SS*DH];    // Q fp32 [b,h,s,e]
__device__ __align__(16) uint32_t g_Kf[(size_t)BB*HH*SS*DH];  // K tf32 frag units
__device__ __align__(16) uint32_t g_Vf[(size_t)BB*HH*DH*SS];  // V tf32 frag units

// ---------------------------------------------------------------------------
// helpers
// ---------------------------------------------------------------------------
__device__ __forceinline__ uint32_t f2tf32(float f) {
    uint32_t r;
    asm("cvt.rna.tf32.f32 %0, %1;" : "=r"(r) : "f"(f));
    return r;
}

__device__ __forceinline__ void mma_tf32(float c[4],
                                         uint32_t a0, uint32_t a1, uint32_t a2, uint32_t a3,
                                         uint32_t b0, uint32_t b1) {
    asm volatile(
        "mma.sync.aligned.m16n8k8.row.col.f32.tf32.tf32.f32 "
        "{%0,%1,%2,%3}, {%4,%5,%6,%7}, {%8,%9}, {%0,%1,%2,%3};"
        : "+f"(c[0]), "+f"(c[1]), "+f"(c[2]), "+f"(c[3])
        : "r"(a0), "r"(a1), "r"(a2), "r"(a3), "r"(b0), "r"(b1));
}

__device__ __forceinline__ void cpa16(uint32_t smem_addr, const void* gptr) {
    asm volatile("cp.async.cg.shared.global [%0], [%1], 16;"
                 :: "r"(smem_addr), "l"(gptr));
}
__device__ __forceinline__ void cpa_commit() {
    asm volatile("cp.async.commit_group;");
}
template <int N>
__device__ __forceinline__ void cpa_wait() {
    asm volatile("cp.async.wait_group %0;" :: "n"(N));
}

// ---------------------------------------------------------------------------
// Kernel 0: pre-round x and W onto the tf32 grid (bits + 0x1000; the mma
// truncates low 13 bits, so net effect == cvt.rna.tf32).
// ---------------------------------------------------------------------------
#define XC (BB*SS*DIN/4)     // uint4 chunks of x
#define WC (WWRD/4)          // uint4 chunks per W matrix

__global__ __launch_bounds__(256)
void round_kernel(const uint4* __restrict__ x, const uint4* __restrict__ wq,
                  const uint4* __restrict__ wk, const uint4* __restrict__ wv) {
    const int stride = gridDim.x * blockDim.x;
    for (int i = blockIdx.x*blockDim.x + threadIdx.x; i < XC + 3*WC; i += stride) {
        uint4 v; uint4* dst;
        if (i < XC) {
            v = x[i];
            dst = (uint4*)g_Xr + i;
        } else {
            int j = i - XC;
            int m = j / WC, r = j - m*WC;
            const uint4* src = (m == 0) ? wq : (m == 1) ? wk : wv;
            v = src[r];
            dst = (uint4*)g_Wr + j;
        }
        v.x += 0x1000u; v.y += 0x1000u; v.z += 0x1000u; v.w += 0x1000u;
        *dst = v;
    }
}

// ---------------------------------------------------------------------------
// Kernel 1: fused QKV projection, zero-conversion cp.async tf32 GEMM.
// grid (4096/128, 12); 512 threads (16 warps: 4m x 4n). 4-stage pipeline,
// one barrier per chunk, 2-deep async overlap.
// ---------------------------------------------------------------------------
#define XSTR 36
#define WSTR 72
#define PXW  (128*XSTR)          // 4608 words: X part of a stage
#define PSTG (PXW + 3*32*WSTR)   // 11520 words per stage
#define PNC  (DIN/32)            // 24 k-chunks

__global__ __launch_bounds__(512, 1)
void qkv_proj_kernel() {
    extern __shared__ uint32_t psm[];

    const int tid = threadIdx.x;
    const int wid = tid >> 5, lane = tid & 31;
    const int tg = lane >> 2, tig = lane & 3;
    const int wm = wid >> 2, wn = wid & 3;
    const int h = blockIdx.y;
    const int rowblk = blockIdx.x * 128;

    const uint32_t* xr = g_Xr + (size_t)rowblk * DIN;
    const uint32_t* wb = g_Wr + (size_t)h * DIN * DH;   // + m*WWRD per matrix

    const uint32_t smem_base = (uint32_t)__cvta_generic_to_shared(psm);

    float acc[3][2][2][4];
    #pragma unroll
    for (int m = 0; m < 3; m++)
        #pragma unroll
        for (int i = 0; i < 2; i++)
            #pragma unroll
            for (int j = 0; j < 2; j++)
                #pragma unroll
                for (int r = 0; r < 4; r++) acc[m][i][j][r] = 0.f;

    auto copy_chunk = [&](int kc, int stage) {
        const uint32_t sb = smem_base + stage * (PSTG*4);
        // X: 1024 16B chunks (128 rows x 8)
        #pragma unroll
        for (int u = 0; u < 2; u++) {
            int idx = tid + u*512, r = idx >> 3, c4 = (idx & 7) * 4;
            cpa16(sb + (r*XSTR + c4)*4, xr + (size_t)r*DIN + kc*32 + c4);
        }
        // W: 1536 16B chunks (3 mats x 32 k x 16)
        #pragma unroll
        for (int u = 0; u < 3; u++) {
            int idx = tid + u*512;
            int m = idx >> 9, rem = idx & 511;
            int k = rem >> 4, n4 = (rem & 15) * 4;
            cpa16(sb + (PXW + m*(32*WSTR) + k*WSTR + n4)*4,
                  wb + (size_t)m*WWRD + (size_t)(kc*32 + k)*DH + n4);
        }
        cpa_commit();
    };

    copy_chunk(0, 0);
    copy_chunk(1, 1);

    for (int kc = 0; kc < PNC; kc++) {
        // Issue the kc+2 fill BEFORE waiting: stage (kc+2)%4's readers
        // finished at iter kc-2, sealed by the barrier at iter kc-1.
        if (kc + 2 < PNC) copy_chunk(kc + 2, (kc + 2) & 3);
        // Chunk kc must be complete; allow up to 2 younger groups in flight.
        if      (kc + 2 < PNC) cpa_wait<2>();
        else if (kc + 1 < PNC) cpa_wait<1>();
        else                   cpa_wait<0>();
        __syncthreads();        // collective visibility of stage kc

        const uint32_t* Xs = psm + (kc & 3) * PSTG;
        const uint32_t* Ws = Xs + PXW;

        #pragma unroll
        for (int kk = 0; kk < 4; kk++) {
            const int k0 = kk * 8;
            uint32_t a[2][4];
            #pragma unroll
            for (int ms = 0; ms < 2; ms++) {
                int r0 = wm*32 + ms*16 + tg;
                a[ms][0] = Xs[(r0    )*XSTR + k0 + tig    ];
                a[ms][1] = Xs[(r0 + 8)*XSTR + k0 + tig    ];
                a[ms][2] = Xs[(r0    )*XSTR + k0 + tig + 4];
                a[ms][3] = Xs[(r0 + 8)*XSTR + k0 + tig + 4];
            }
            #pragma unroll
            for (int m = 0; m < 3; m++) {
                #pragma unroll
                for (int j = 0; j < 2; j++) {
                    int n0 = wn*16 + j*8 + tg;
                    uint32_t b0 = Ws[m*(32*WSTR) + (k0 + tig    )*WSTR + n0];
                    uint32_t b1 = Ws[m*(32*WSTR) + (k0 + tig + 4)*WSTR + n0];
                    #pragma unroll
                    for (int ms = 0; ms < 2; ms++)
                        mma_tf32(acc[m][ms][j], a[ms][0], a[ms][1], a[ms][2], a[ms][3], b0, b1);
                }
            }
        }
    }
    __syncthreads();   // all warps finished mma before smem reuse below

    // ------------------- Epilogue -------------------
    const int b = rowblk >> 10;
    const int s0 = rowblk & 1023;
    const size_t base = (((size_t)b*HH + h)*SS);

    // Q: fp32 direct
    #pragma unroll
    for (int ms = 0; ms < 2; ms++) {
        int r0 = s0 + wm*32 + ms*16 + tg;
        #pragma unroll
        for (int j = 0; j < 2; j++) {
            int c0 = wn*16 + j*8 + tig*2;
            #pragma unroll
            for (int half = 0; half < 2; half++) {
                *(float2*)&g_Qf[(base + r0 + half*8)*DH + c0] =
                    make_float2(acc[0][ms][j][half*2], acc[0][ms][j][half*2+1]);
            }
        }
    }

    // K, V: bounce through smem (fp32, stride 68), emit unit layouts linearly.
    float* Ksm = (float*)psm;                 // [128][68]
    float* Vsm = (float*)psm + 128*68;        // [128][68]
    #pragma unroll
    for (int ms = 0; ms < 2; ms++) {
        int rl = wm*32 + ms*16 + tg;
        #pragma unroll
        for (int j = 0; j < 2; j++) {
            int c0 = wn*16 + j*8 + tig*2;
            #pragma unroll
            for (int half = 0; half < 2; half++) {
                *(float2*)&Ksm[(rl + half*8)*68 + c0] =
                    make_float2(acc[1][ms][j][half*2], acc[1][ms][j][half*2+1]);
                *(float2*)&Vsm[(rl + half*8)*68 + c0] =
                    make_float2(acc[2][ms][j][half*2], acc[2][ms][j][half*2+1]);
            }
        }
    }
    __syncthreads();

    // Kf: 4096 8B units {k(c), k(c+4)} (c = k8*8+tgu), linear stores
    {
        uint32_t* kf = g_Kf + (base + s0)*DH;
        #pragma unroll
        for (int u = 0; u < 8; u++) {
            int idx = tid + u*512;            // 0..4095
            int sl = idx >> 5, un = idx & 31;
            int k8 = un >> 2, tgu = un & 3;
            int c = k8*8 + tgu;
            float f0 = Ksm[sl*68 + c];
            float f1 = Ksm[sl*68 + c + 4];
            *(uint2*)&kf[(size_t)sl*64 + un*2] = make_uint2(f2tf32(f0), f2tf32(f1));
        }
    }
    // Vf: 4096 8B units {v(s), v(s+4)}
    {
        uint32_t* vf = g_Vf + ((size_t)b*HH + h) * (DH*SS);
        #pragma unroll
        for (int u = 0; u < 8; u++) {
            int idx = tid + u*512;            // 0..4095
            int e = idx >> 6, rem = idx & 63;
            int ks8l = rem >> 2, tgu = rem & 3;
            int sl = ks8l*8 + tgu;
            float f0 = Vsm[(sl    )*68 + e];
            float f1 = Vsm[(sl + 4)*68 + e];
            *(uint2*)&vf[(size_t)e*1024 + ((s0 >> 3) + ks8l)*8 + tgu*2] =
                make_uint2(f2tf32(f0), f2tf32(f1));
        }
    }
}

// ---------------------------------------------------------------------------
// Kernel 2: tensor-core causal flash attention. Now 3 CTAs/SM target.
// grid (16, 12, 4); 128 threads; cp.async 2-stage; Q pre-scaled by 0.125.
// ---------------------------------------------------------------------------
#define STW 8192     // words per stage: K 4096 + V 4096

__global__ __launch_bounds__(128, 3)
void attn_kernel(float* __restrict__ out) {
    extern __shared__ uint32_t smu[];

    const int mt = gridDim.x - 1 - blockIdx.x;
    const int h = blockIdx.y, b = blockIdx.z;
    const int tid = threadIdx.x, wid = tid >> 5, lane = tid & 31;
    const int tg = lane >> 2, tig = lane & 3;
    const int m0 = mt * 64;
    const size_t bh = ((size_t)b*HH + h) * SS;
    const float*    gqf = g_Qf + bh*DH;
    const uint32_t* gkf = g_Kf + bh*DH;
    const uint32_t* gvf = g_Vf + ((size_t)b*HH + h) * (DH*SS);

    const uint32_t smem_base = (uint32_t)__cvta_generic_to_shared(smu);

    // Q fragments: pre-scaled by 0.125 (exact), split big/small tf32
    uint32_t qb[8][4], qs[8][4];
    {
        const int r0 = m0 + wid*16 + tg;
        #pragma unroll
        for (int k = 0; k < 8; k++) {
            float f[4];
            f[0] = 0.125f * gqf[(size_t)(r0    )*DH + k*8 + tig    ];
            f[1] = 0.125f * gqf[(size_t)(r0 + 8)*DH + k*8 + tig    ];
            f[2] = 0.125f * gqf[(size_t)(r0    )*DH + k*8 + tig + 4];
            f[3] = 0.125f * gqf[(size_t)(r0 + 8)*DH + k*8 + tig + 4];
            #pragma unroll
            for (int i = 0; i < 4; i++) {
                qb[k][i] = f2tf32(f[i]);
                qs[k][i] = f2tf32(f[i] - __uint_as_float(qb[k][i]));
            }
        }
    }

    auto copy_tile = [&](int kt, int stage) {
        const uint32_t sb = smem_base + stage * (STW*4);
        #pragma unroll
        for (int u = 0; u < 8; u++) {
            int idx = tid + u*128;
            int s = idx >> 4, cc = idx & 15;
            int ccs = cc ^ ((s & 7) << 1);
            cpa16(sb + s*256 + ccs*16,
                  gkf + ((size_t)(kt*64 + s)*64 + cc*4));
        }
        #pragma unroll
        for (int u = 0; u < 8; u++) {
            int idx = tid + u*128;
            int e = idx >> 4, p = idx & 15;
            int un = 2*p;
            int usw = un ^ ((e & 7) << 2);
            cpa16(sb + 4096*4 + (e*32 + usw)*8,
                  gvf + (size_t)e*1024 + (kt*32 + un)*2);
        }
        cpa_commit();
    };

    float o[8][4];
    #pragma unroll
    for (int j = 0; j < 8; j++)
        #pragma unroll
        for (int i = 0; i < 4; i++) o[j][i] = 0.f;
    float mrow[2] = {-1e30f, -1e30f};
    float lrow[2] = {0.f, 0.f};

    copy_tile(0, 0);

    for (int kt = 0; kt <= mt; kt++) {
        if (kt < mt) { copy_tile(kt+1, (kt+1)&1); cpa_wait<1>(); }
        else         { cpa_wait<0>(); }
        __syncthreads();

        const uint32_t* Kst = smu + (kt&1)*STW;
        const uint32_t* Vst = Kst + 4096;

        float c[8][4];
        #pragma unroll
        for (int j = 0; j < 8; j++)
            #pragma unroll
            for (int i = 0; i < 4; i++) c[j][i] = 0.f;

        #pragma unroll
        for (int k = 0; k < 8; k++) {
            const int un = k*4 + tig;
            const int cc = un >> 1, half = un & 1;
            #pragma unroll
            for (int j = 0; j < 8; j++) {
                const int nr = j*8 + tg;
                int ccs = cc ^ ((nr & 7) << 1);
                uint2 kv = *(const uint2*)&Kst[nr*64 + ccs*4 + half*2];
                mma_tf32(c[j], qb[k][0], qb[k][1], qb[k][2], qb[k][3], kv.x, kv.y);
                mma_tf32(c[j], qs[k][0], qs[k][1], qs[k][2], qs[k][3], kv.x, kv.y);
            }
        }

        if (kt == mt) {       // diagonal tile: causal mask
            const int rl0 = wid*16 + tg, rl1 = rl0 + 8;
            #pragma unroll
            for (int j = 0; j < 8; j++) {
                int c0 = j*8 + 2*tig, c1 = c0 + 1;
                if (c0 > rl0) c[j][0] = -1e30f;
                if (c1 > rl0) c[j][1] = -1e30f;
                if (c0 > rl1) c[j][2] = -1e30f;
                if (c1 > rl1) c[j][3] = -1e30f;
            }
        }

        float alpha[2];
        #pragma unroll
        for (int h2 = 0; h2 < 2; h2++) {
            float mx = -1e30f;
            #pragma unroll
            for (int j = 0; j < 8; j++) {
                mx = fmaxf(mx, c[j][h2*2]);
                mx = fmaxf(mx, c[j][h2*2 + 1]);
            }
            mx = fmaxf(mx, __shfl_xor_sync(0xffffffffu, mx, 1));
            mx = fmaxf(mx, __shfl_xor_sync(0xffffffffu, mx, 2));
            float mnew = fmaxf(mrow[h2], mx);
            float sum = 0.f;
            #pragma unroll
            for (int j = 0; j < 8; j++) {
                float p0 = __expf(c[j][h2*2]     - mnew);
                float p1 = __expf(c[j][h2*2 + 1] - mnew);
                c[j][h2*2]     = p0;
                c[j][h2*2 + 1] = p1;
                sum += p0 + p1;
            }
            sum += __shfl_xor_sync(0xffffffffu, sum, 1);
            sum += __shfl_xor_sync(0xffffffffu, sum, 2);
            alpha[h2] = __expf(mrow[h2] - mnew);
            mrow[h2] = mnew;
            lrow[h2] = lrow[h2]*alpha[h2] + sum;
        }

        #pragma unroll
        for (int j = 0; j < 8; j++) {
            o[j][0] *= alpha[0]; o[j][1] *= alpha[0];
            o[j][2] *= alpha[1]; o[j][3] *= alpha[1];
        }

        const int src0 = (tg << 2) + (tig >> 1);
        const int src1 = src0 + 2;
        const bool odd = (tig & 1);
        #pragma unroll
        for (int k = 0; k < 8; k++) {
            float e0 = __shfl_sync(0xffffffffu, c[k][0], src0);
            float o0 = __shfl_sync(0xffffffffu, c[k][1], src0);
            float e1 = __shfl_sync(0xffffffffu, c[k][2], src0);
            float o1 = __shfl_sync(0xffffffffu, c[k][3], src0);
            float e2 = __shfl_sync(0xffffffffu, c[k][0], src1);
            float o2 = __shfl_sync(0xffffffffu, c[k][1], src1);
            float e3 = __shfl_sync(0xffffffffu, c[k][2], src1);
            float o3 = __shfl_sync(0xffffffffu, c[k][3], src1);
            uint32_t a0 = f2tf32(odd ? o0 : e0);
            uint32_t a1 = f2tf32(odd ? o1 : e1);
            uint32_t a2 = f2tf32(odd ? o2 : e2);
            uint32_t a3 = f2tf32(odd ? o3 : e3);

            const int usw = (k*4 + tig) ^ (tg << 2);
            #pragma unroll
            for (int jn = 0; jn < 8; jn++) {
                const int e = jn*8 + tg;
                uint2 vf = *(const uint2*)&Vst[(e*32 + usw)*2];
                mma_tf32(o[jn], a0, a1, a2, a3, vf.x, vf.y);
            }
        }
        __syncthreads();
    }

    const float inv0 = 1.f / lrow[0], inv1 = 1.f / lrow[1];
    const int r0 = m0 + wid*16 + tg;
    #pragma unroll
    for (int j = 0; j < 8; j++) {
        int col = h*DH + j*8 + 2*tig;
        *(float2*)&out[((size_t)b*SS + r0    )*(HH*DH) + col] =
            make_float2(o[j][0]*inv0, o[j][1]*inv0);
        *(float2*)&out[((size_t)b*SS + r0 + 8)*(HH*DH) + col] =
            make_float2(o[j][2]*inv1, o[j][3]*inv1);
    }
}

// ---------------------------------------------------------------------------
extern "C" void kernel_launch(void* const* d_in, const int* in_sizes, int n_in,
                              void* d_out, int out_size) {
    const float* x  = (const float*)d_in[0];
    const float* Wq = (const float*)d_in[1];
    const float* Wk = (const float*)d_in[2];
    const float* Wv = (const float*)d_in[3];
    float* out = (float*)d_out;

    round_kernel<<<1184, 256>>>((const uint4*)x, (const uint4*)Wq,
                                (const uint4*)Wk, (const uint4*)Wv);

    const int proj_smem = 4 * PSTG * (int)sizeof(uint32_t);        // 184,320 B
    cudaFuncSetAttribute(qkv_proj_kernel, cudaFuncAttributeMaxDynamicSharedMemorySize,
                         proj_smem);
    qkv_proj_kernel<<<dim3((BB*SS)/128, HH), 512, proj_smem>>>();

    const int attn_smem = 2 * STW * (int)sizeof(uint32_t);         // 65,536 B
    cudaFuncSetAttribute(attn_kernel, cudaFuncAttributeMaxDynamicSharedMemorySize,
                         attn_smem);
    attn_kernel<<<dim3(SS/64, HH, BB), 128, attn_smem>>>(out);
}

// round 11
// speedup vs baseline: 1.1287x; 1.0439x over previous
#include <cuda_runtime.h>
#include <cstdint>

// Problem constants
#define BB   4
#define SS   1024
#define DIN  768
#define HH   12
#define DH   64
#define WWRD (HH*DIN*DH)     // words per weight matrix (589824)

// Scratch (device globals; no allocs allowed).
__device__ __align__(16) uint32_t g_Xr[BB*SS*DIN];      // x pre-rounded to tf32 grid
__device__ __align__(16) uint32_t g_Wr[3*WWRD];         // Wq|Wk|Wv pre-rounded
__device__ __align__(16) float    g_Qf[BB*HH*SS*DH];    // Q fp32 [b,h,s,e]
__device__ __align__(16) uint32_t g_Kf[(size_t)BB*HH*SS*DH];  // K tf32 frag units
__device__ __align__(16) uint32_t g_Vf[(size_t)BB*HH*DH*SS];  // V tf32 frag units

// ---------------------------------------------------------------------------
// helpers
// ---------------------------------------------------------------------------
__device__ __forceinline__ uint32_t f2tf32(float f) {
    uint32_t r;
    asm("cvt.rna.tf32.f32 %0, %1;" : "=r"(r) : "f"(f));
    return r;
}

__device__ __forceinline__ void mma_tf32(float c[4],
                                         uint32_t a0, uint32_t a1, uint32_t a2, uint32_t a3,
                                         uint32_t b0, uint32_t b1) {
    asm volatile(
        "mma.sync.aligned.m16n8k8.row.col.f32.tf32.tf32.f32 "
        "{%0,%1,%2,%3}, {%4,%5,%6,%7}, {%8,%9}, {%0,%1,%2,%3};"
        : "+f"(c[0]), "+f"(c[1]), "+f"(c[2]), "+f"(c[3])
        : "r"(a0), "r"(a1), "r"(a2), "r"(a3), "r"(b0), "r"(b1));
}

__device__ __forceinline__ void cpa16(uint32_t smem_addr, const void* gptr) {
    asm volatile("cp.async.cg.shared.global [%0], [%1], 16;"
                 :: "r"(smem_addr), "l"(gptr));
}
__device__ __forceinline__ void cpa_commit() {
    asm volatile("cp.async.commit_group;");
}
template <int N>
__device__ __forceinline__ void cpa_wait() {
    asm volatile("cp.async.wait_group %0;" :: "n"(N));
}

// ---------------------------------------------------------------------------
// Kernel 0: pre-round x and W onto the tf32 grid (bits + 0x1000; the mma
// truncates low 13 bits, so net effect == cvt.rna.tf32).
// ---------------------------------------------------------------------------
#define XC (BB*SS*DIN/4)     // uint4 chunks of x
#define WC (WWRD/4)          // uint4 chunks per W matrix

__global__ __launch_bounds__(256)
void round_kernel(const uint4* __restrict__ x, const uint4* __restrict__ wq,
                  const uint4* __restrict__ wk, const uint4* __restrict__ wv) {
    const int stride = gridDim.x * blockDim.x;
    for (int i = blockIdx.x*blockDim.x + threadIdx.x; i < XC + 3*WC; i += stride) {
        uint4 v; uint4* dst;
        if (i < XC) {
            v = x[i];
            dst = (uint4*)g_Xr + i;
        } else {
            int j = i - XC;
            int m = j / WC, r = j - m*WC;
            const uint4* src = (m == 0) ? wq : (m == 1) ? wk : wv;
            v = src[r];
            dst = (uint4*)g_Wr + j;
        }
        v.x += 0x1000u; v.y += 0x1000u; v.z += 0x1000u; v.w += 0x1000u;
        *dst = v;
    }
}

// ---------------------------------------------------------------------------
// Kernel 1: fused QKV projection, zero-conversion cp.async tf32 GEMM.
// grid (32, 12, 2 n-splits); 256 threads (8 warps: 4m x 2n). 2 CTAs/SM.
// Block tile: M=128, N=32 per matrix x3. Warp tile m32 x n16 x3.
// 3-stage ring, one barrier/chunk, copy issued after the barrier.
// ---------------------------------------------------------------------------
#define XSTR 36
#define WSTR2 40
#define PXW  (128*XSTR)           // 4608 words: X part of a stage
#define PWW  (3*32*WSTR2)         // 3840 words: W part of a stage
#define PSTG (PXW + PWW)          // 8448 words per stage
#define PNC  (DIN/32)             // 24 k-chunks

__global__ __launch_bounds__(256, 2)
void qkv_proj_kernel() {
    extern __shared__ uint32_t psm[];

    const int tid = threadIdx.x;
    const int wid = tid >> 5, lane = tid & 31;
    const int tg = lane >> 2, tig = lane & 3;
    const int wm = wid >> 1, wn = wid & 1;      // 4m x 2n warps
    const int h = blockIdx.y;
    const int ns = blockIdx.z;                  // n-split: cols [ns*32, ns*32+32)
    const int rowblk = blockIdx.x * 128;

    const uint32_t* xr = g_Xr + (size_t)rowblk * DIN;
    const uint32_t* wb = g_Wr + (size_t)h * DIN * DH + ns*32;

    const uint32_t smem_base = (uint32_t)__cvta_generic_to_shared(psm);

    float acc[3][2][2][4];
    #pragma unroll
    for (int m = 0; m < 3; m++)
        #pragma unroll
        for (int i = 0; i < 2; i++)
            #pragma unroll
            for (int j = 0; j < 2; j++)
                #pragma unroll
                for (int r = 0; r < 4; r++) acc[m][i][j][r] = 0.f;

    auto copy_chunk = [&](int kc, int stage) {
        const uint32_t sb = smem_base + stage * (PSTG*4);
        // X: 1024 16B chunks (128 rows x 8)
        #pragma unroll
        for (int u = 0; u < 4; u++) {
            int idx = tid + u*256, r = idx >> 3, c4 = (idx & 7) * 4;
            cpa16(sb + (r*XSTR + c4)*4, xr + (size_t)r*DIN + kc*32 + c4);
        }
        // W: 768 16B chunks (3 mats x 32 k x 8)
        #pragma unroll
        for (int u = 0; u < 3; u++) {
            int k = tid >> 3, n4 = (tid & 7) * 4;
            cpa16(sb + (PXW + u*(32*WSTR2) + k*WSTR2 + n4)*4,
                  wb + (size_t)u*WWRD + (size_t)(kc*32 + k)*DH + n4);
        }
        cpa_commit();
    };

    copy_chunk(0, 0);
    copy_chunk(1, 1);

    for (int kc = 0; kc < PNC; kc++) {
        if (kc + 1 < PNC) cpa_wait<1>(); else cpa_wait<0>();
        __syncthreads();
        if (kc + 2 < PNC) copy_chunk(kc + 2, (kc + 2) % 3);

        const uint32_t* Xs = psm + (kc % 3) * PSTG;
        const uint32_t* Ws = Xs + PXW;

        #pragma unroll
        for (int kk = 0; kk < 4; kk++) {
            const int k0 = kk * 8;
            uint32_t a[2][4];
            #pragma unroll
            for (int ms = 0; ms < 2; ms++) {
                int r0 = wm*32 + ms*16 + tg;
                a[ms][0] = Xs[(r0    )*XSTR + k0 + tig    ];
                a[ms][1] = Xs[(r0 + 8)*XSTR + k0 + tig    ];
                a[ms][2] = Xs[(r0    )*XSTR + k0 + tig + 4];
                a[ms][3] = Xs[(r0 + 8)*XSTR + k0 + tig + 4];
            }
            #pragma unroll
            for (int m = 0; m < 3; m++) {
                #pragma unroll
                for (int j = 0; j < 2; j++) {
                    int n0 = wn*16 + j*8 + tg;
                    uint32_t b0 = Ws[m*(32*WSTR2) + (k0 + tig    )*WSTR2 + n0];
                    uint32_t b1 = Ws[m*(32*WSTR2) + (k0 + tig + 4)*WSTR2 + n0];
                    #pragma unroll
                    for (int ms = 0; ms < 2; ms++)
                        mma_tf32(acc[m][ms][j], a[ms][0], a[ms][1], a[ms][2], a[ms][3], b0, b1);
                }
            }
        }
    }
    __syncthreads();   // all warps finished mma before smem reuse below

    // ------------------- Epilogue -------------------
    const int b = rowblk >> 10;
    const int s0 = rowblk & 1023;
    const size_t base = (((size_t)b*HH + h)*SS);

    // Q: fp32 direct (this CTA's 32 columns)
    #pragma unroll
    for (int ms = 0; ms < 2; ms++) {
        int r0 = s0 + wm*32 + ms*16 + tg;
        #pragma unroll
        for (int j = 0; j < 2; j++) {
            int c0 = ns*32 + wn*16 + j*8 + tig*2;
            #pragma unroll
            for (int half = 0; half < 2; half++) {
                *(float2*)&g_Qf[(base + r0 + half*8)*DH + c0] =
                    make_float2(acc[0][ms][j][half*2], acc[0][ms][j][half*2+1]);
            }
        }
    }

    // K, V: bounce through smem (fp32, local 32 cols, stride 36), emit units.
    float* Ksm = (float*)psm;                 // [128][36]
    float* Vsm = (float*)psm + 128*36;        // [128][36]
    #pragma unroll
    for (int ms = 0; ms < 2; ms++) {
        int rl = wm*32 + ms*16 + tg;
        #pragma unroll
        for (int j = 0; j < 2; j++) {
            int c0 = wn*16 + j*8 + tig*2;     // local column
            #pragma unroll
            for (int half = 0; half < 2; half++) {
                *(float2*)&Ksm[(rl + half*8)*36 + c0] =
                    make_float2(acc[1][ms][j][half*2], acc[1][ms][j][half*2+1]);
                *(float2*)&Vsm[(rl + half*8)*36 + c0] =
                    make_float2(acc[2][ms][j][half*2], acc[2][ms][j][half*2+1]);
            }
        }
    }
    __syncthreads();

    // Kf: this CTA's 2048 8B units (k8 in [ns*4, ns*4+4)), linear stores
    {
        uint32_t* kf = g_Kf + (base + s0)*DH;
        #pragma unroll
        for (int u = 0; u < 8; u++) {
            int idx = tid + u*256;            // 0..2047
            int sl = idx >> 4, unl = idx & 15;
            int k8l = unl >> 2, tgu = unl & 3;
            int cl = k8l*8 + tgu;
            float f0 = Ksm[sl*36 + cl];
            float f1 = Ksm[sl*36 + cl + 4];
            int un = ns*16 + unl;
            *(uint2*)&kf[(size_t)sl*64 + un*2] = make_uint2(f2tf32(f0), f2tf32(f1));
        }
    }
    // Vf: this CTA's 2048 8B units (e in [ns*32, ns*32+32))
    {
        uint32_t* vf = g_Vf + ((size_t)b*HH + h) * (DH*SS);
        #pragma unroll
        for (int u = 0; u < 8; u++) {
            int idx = tid + u*256;            // 0..2047
            int el = idx >> 6, rem = idx & 63;
            int ks8l = rem >> 2, tgu = rem & 3;
            int sl = ks8l*8 + tgu;
            float f0 = Vsm[(sl    )*36 + el];
            float f1 = Vsm[(sl + 4)*36 + el];
            *(uint2*)&vf[(size_t)(ns*32 + el)*1024 + ((s0 >> 3) + ks8l)*8 + tgu*2] =
                make_uint2(f2tf32(f0), f2tf32(f1));
        }
    }
}

// ---------------------------------------------------------------------------
// Kernel 2: tensor-core causal flash attention. 2 CTAs/SM, 3-stage ring,
// one barrier per tile (copy issued after the barrier). Q pre-scaled 0.125.
// grid (16, 12, 4); 128 threads (4 warps, warp = 16 q-rows).
// ---------------------------------------------------------------------------
#define STW 8192     // words per stage: K 4096 + V 4096

__global__ __launch_bounds__(128, 2)
void attn_kernel(float* __restrict__ out) {
    extern __shared__ uint32_t smu[];

    const int mt = gridDim.x - 1 - blockIdx.x;
    const int h = blockIdx.y, b = blockIdx.z;
    const int tid = threadIdx.x, wid = tid >> 5, lane = tid & 31;
    const int tg = lane >> 2, tig = lane & 3;
    const int m0 = mt * 64;
    const size_t bh = ((size_t)b*HH + h) * SS;
    const float*    gqf = g_Qf + bh*DH;
    const uint32_t* gkf = g_Kf + bh*DH;
    const uint32_t* gvf = g_Vf + ((size_t)b*HH + h) * (DH*SS);

    const uint32_t smem_base = (uint32_t)__cvta_generic_to_shared(smu);

    // Q fragments: pre-scaled by 0.125 (exact), split big/small tf32
    uint32_t qb[8][4], qs[8][4];
    {
        const int r0 = m0 + wid*16 + tg;
        #pragma unroll
        for (int k = 0; k < 8; k++) {
            float f[4];
            f[0] = 0.125f * gqf[(size_t)(r0    )*DH + k*8 + tig    ];
            f[1] = 0.125f * gqf[(size_t)(r0 + 8)*DH + k*8 + tig    ];
            f[2] = 0.125f * gqf[(size_t)(r0    )*DH + k*8 + tig + 4];
            f[3] = 0.125f * gqf[(size_t)(r0 + 8)*DH + k*8 + tig + 4];
            #pragma unroll
            for (int i = 0; i < 4; i++) {
                qb[k][i] = f2tf32(f[i]);
                qs[k][i] = f2tf32(f[i] - __uint_as_float(qb[k][i]));
            }
        }
    }

    auto copy_tile = [&](int kt, int stage) {
        const uint32_t sb = smem_base + stage * (STW*4);
        #pragma unroll
        for (int u = 0; u < 8; u++) {
            int idx = tid + u*128;
            int s = idx >> 4, cc = idx & 15;
            int ccs = cc ^ ((s & 7) << 1);
            cpa16(sb + s*256 + ccs*16,
                  gkf + ((size_t)(kt*64 + s)*64 + cc*4));
        }
        #pragma unroll
        for (int u = 0; u < 8; u++) {
            int idx = tid + u*128;
            int e = idx >> 4, p = idx & 15;
            int un = 2*p;
            int usw = un ^ ((e & 7) << 2);
            cpa16(sb + 4096*4 + (e*32 + usw)*8,
                  gvf + (size_t)e*1024 + (kt*32 + un)*2);
        }
        cpa_commit();
    };

    float o[8][4];
    #pragma unroll
    for (int j = 0; j < 8; j++)
        #pragma unroll
        for (int i = 0; i < 4; i++) o[j][i] = 0.f;
    float mrow[2] = {-1e30f, -1e30f};
    float lrow[2] = {0.f, 0.f};

    copy_tile(0, 0);
    if (mt >= 1) copy_tile(1, 1);

    for (int kt = 0; kt <= mt; kt++) {
        if (kt + 1 <= mt) cpa_wait<1>(); else cpa_wait<0>();
        __syncthreads();
        if (kt + 2 <= mt) copy_tile(kt + 2, (kt + 2) % 3);

        const uint32_t* Kst = smu + (kt % 3)*STW;
        const uint32_t* Vst = Kst + 4096;

        float c[8][4];
        #pragma unroll
        for (int j = 0; j < 8; j++)
            #pragma unroll
            for (int i = 0; i < 4; i++) c[j][i] = 0.f;

        #pragma unroll
        for (int k = 0; k < 8; k++) {
            const int un = k*4 + tig;
            const int cc = un >> 1, half = un & 1;
            #pragma unroll
            for (int j = 0; j < 8; j++) {
                const int nr = j*8 + tg;
                int ccs = cc ^ ((nr & 7) << 1);
                uint2 kv = *(const uint2*)&Kst[nr*64 + ccs*4 + half*2];
                mma_tf32(c[j], qb[k][0], qb[k][1], qb[k][2], qb[k][3], kv.x, kv.y);
                mma_tf32(c[j], qs[k][0], qs[k][1], qs[k][2], qs[k][3], kv.x, kv.y);
            }
        }

        if (kt == mt) {       // diagonal tile: causal mask
            const int rl0 = wid*16 + tg, rl1 = rl0 + 8;
            #pragma unroll
            for (int j = 0; j < 8; j++) {
                int c0 = j*8 + 2*tig, c1 = c0 + 1;
                if (c0 > rl0) c[j][0] = -1e30f;
                if (c1 > rl0) c[j][1] = -1e30f;
                if (c0 > rl1) c[j][2] = -1e30f;
                if (c1 > rl1) c[j][3] = -1e30f;
            }
        }

        float alpha[2];
        #pragma unroll
        for (int h2 = 0; h2 < 2; h2++) {
            float mx = -1e30f;
            #pragma unroll
            for (int j = 0; j < 8; j++) {
                mx = fmaxf(mx, c[j][h2*2]);
                mx = fmaxf(mx, c[j][h2*2 + 1]);
            }
            mx = fmaxf(mx, __shfl_xor_sync(0xffffffffu, mx, 1));
            mx = fmaxf(mx, __shfl_xor_sync(0xffffffffu, mx, 2));
            float mnew = fmaxf(mrow[h2], mx);
            float sum = 0.f;
            #pragma unroll
            for (int j = 0; j < 8; j++) {
                float p0 = __expf(c[j][h2*2]     - mnew);
                float p1 = __expf(c[j][h2*2 + 1] - mnew);
                c[j][h2*2]     = p0;
                c[j][h2*2 + 1] = p1;
                sum += p0 + p1;
            }
            sum += __shfl_xor_sync(0xffffffffu, sum, 1);
            sum += __shfl_xor_sync(0xffffffffu, sum, 2);
            alpha[h2] = __expf(mrow[h2] - mnew);
            mrow[h2] = mnew;
            lrow[h2] = lrow[h2]*alpha[h2] + sum;
        }

        #pragma unroll
        for (int j = 0; j < 8; j++) {
            o[j][0] *= alpha[0]; o[j][1] *= alpha[0];
            o[j][2] *= alpha[1]; o[j][3] *= alpha[1];
        }

        const int src0 = (tg << 2) + (tig >> 1);
        const int src1 = src0 + 2;
        const bool odd = (tig & 1);
        #pragma unroll
        for (int k = 0; k < 8; k++) {
            float e0 = __shfl_sync(0xffffffffu, c[k][0], src0);
            float o0 = __shfl_sync(0xffffffffu, c[k][1], src0);
            float e1 = __shfl_sync(0xffffffffu, c[k][2], src0);
            float o1 = __shfl_sync(0xffffffffu, c[k][3], src0);
            float e2 = __shfl_sync(0xffffffffu, c[k][0], src1);
            float o2 = __shfl_sync(0xffffffffu, c[k][1], src1);
            float e3 = __shfl_sync(0xffffffffu, c[k][2], src1);
            float o3 = __shfl_sync(0xffffffffu, c[k][3], src1);
            uint32_t a0 = f2tf32(odd ? o0 : e0);
            uint32_t a1 = f2tf32(odd ? o1 : e1);
            uint32_t a2 = f2tf32(odd ? o2 : e2);
            uint32_t a3 = f2tf32(odd ? o3 : e3);

            const int usw = (k*4 + tig) ^ (tg << 2);
            #pragma unroll
            for (int jn = 0; jn < 8; jn++) {
                const int e = jn*8 + tg;
                uint2 vf = *(const uint2*)&Vst[(e*32 + usw)*2];
                mma_tf32(o[jn], a0, a1, a2, a3, vf.x, vf.y);
            }
        }
        // no trailing barrier: stage reuse is sealed by the barrier at the
        // top of iteration kt+2, which follows all threads' compute of kt.
    }

    const float inv0 = 1.f / lrow[0], inv1 = 1.f / lrow[1];
    const int r0 = m0 + wid*16 + tg;
    #pragma unroll
    for (int j = 0; j < 8; j++) {
        int col = h*DH + j*8 + 2*tig;
        *(float2*)&out[((size_t)b*SS + r0    )*(HH*DH) + col] =
            make_float2(o[j][0]*inv0, o[j][1]*inv0);
        *(float2*)&out[((size_t)b*SS + r0 + 8)*(HH*DH) + col] =
            make_float2(o[j][2]*inv1, o[j][3]*inv1);
    }
}

// ---------------------------------------------------------------------------
extern "C" void kernel_launch(void* const* d_in, const int* in_sizes, int n_in,
                              void* d_out, int out_size) {
    const float* x  = (const float*)d_in[0];
    const float* Wq = (const float*)d_in[1];
    const float* Wk = (const float*)d_in[2];
    const float* Wv = (const float*)d_in[3];
    float* out = (float*)d_out;

    round_kernel<<<1184, 256>>>((const uint4*)x, (const uint4*)Wq,
                                (const uint4*)Wk, (const uint4*)Wv);

    const int proj_smem = 3 * PSTG * (int)sizeof(uint32_t);        // 101,376 B
    cudaFuncSetAttribute(qkv_proj_kernel, cudaFuncAttributeMaxDynamicSharedMemorySize,
                         proj_smem);
    qkv_proj_kernel<<<dim3((BB*SS)/128, HH, 2), 256, proj_smem>>>();

    const int attn_smem = 3 * STW * (int)sizeof(uint32_t);         // 98,304 B
    cudaFuncSetAttribute(attn_kernel, cudaFuncAttributeMaxDynamicSharedMemorySize,
                         attn_smem);
    attn_kernel<<<dim3(SS/64, HH, BB), 128, attn_smem>>>(out);
}

// round 12
// speedup vs baseline: 1.2263x; 1.0865x over previous
#include <cuda_runtime.h>
#include <cstdint>

// Problem constants
#define BB   4
#define SS   1024
#define DIN  768
#define HH   12
#define DH   64
#define WWRD (HH*DIN*DH)     // words per weight matrix (589824)

// Scratch (device globals; no allocs allowed).
__device__ __align__(16) uint32_t g_Xr[BB*SS*DIN];      // x pre-rounded to tf32 grid
__device__ __align__(16) uint32_t g_Wr[3*WWRD];         // Wq|Wk|Wv pre-rounded
__device__ __align__(16) float    g_Qf[BB*HH*SS*DH];    // Q fp32 [b,h,s,e]
__device__ __align__(16) uint32_t g_Kf[(size_t)BB*HH*SS*DH];  // K tf32 frag units
__device__ __align__(16) uint32_t g_Vf[(size_t)BB*HH*DH*SS];  // V tf32 frag units

// ---------------------------------------------------------------------------
// helpers
// ---------------------------------------------------------------------------
__device__ __forceinline__ uint32_t f2tf32(float f) {
    uint32_t r;
    asm("cvt.rna.tf32.f32 %0, %1;" : "=r"(r) : "f"(f));
    return r;
}

__device__ __forceinline__ void mma_tf32(float c[4],
                                         uint32_t a0, uint32_t a1, uint32_t a2, uint32_t a3,
                                         uint32_t b0, uint32_t b1) {
    asm volatile(
        "mma.sync.aligned.m16n8k8.row.col.f32.tf32.tf32.f32 "
        "{%0,%1,%2,%3}, {%4,%5,%6,%7}, {%8,%9}, {%0,%1,%2,%3};"
        : "+f"(c[0]), "+f"(c[1]), "+f"(c[2]), "+f"(c[3])
        : "r"(a0), "r"(a1), "r"(a2), "r"(a3), "r"(b0), "r"(b1));
}

__device__ __forceinline__ void cpa16(uint32_t smem_addr, const void* gptr) {
    asm volatile("cp.async.cg.shared.global [%0], [%1], 16;"
                 :: "r"(smem_addr), "l"(gptr));
}
__device__ __forceinline__ void cpa_commit() {
    asm volatile("cp.async.commit_group;");
}
template <int N>
__device__ __forceinline__ void cpa_wait() {
    asm volatile("cp.async.wait_group %0;" :: "n"(N));
}

// ---------------------------------------------------------------------------
// Kernel 0: pre-round x and W onto the tf32 grid (bits + 0x1000; the mma
// truncates low 13 bits, so net effect == cvt.rna.tf32).
// ---------------------------------------------------------------------------
#define XC (BB*SS*DIN/4)     // uint4 chunks of x
#define WC (WWRD/4)          // uint4 chunks per W matrix

__global__ __launch_bounds__(256)
void round_kernel(const uint4* __restrict__ x, const uint4* __restrict__ wq,
                  const uint4* __restrict__ wk, const uint4* __restrict__ wv) {
    const int stride = gridDim.x * blockDim.x;
    for (int i = blockIdx.x*blockDim.x + threadIdx.x; i < XC + 3*WC; i += stride) {
        uint4 v; uint4* dst;
        if (i < XC) {
            v = x[i];
            dst = (uint4*)g_Xr + i;
        } else {
            int j = i - XC;
            int m = j / WC, r = j - m*WC;
            const uint4* src = (m == 0) ? wq : (m == 1) ? wk : wv;
            v = src[r];
            dst = (uint4*)g_Wr + j;
        }
        v.x += 0x1000u; v.y += 0x1000u; v.z += 0x1000u; v.w += 0x1000u;
        *dst = v;
    }
}

// ---------------------------------------------------------------------------
// Kernel 1: fused QKV projection, zero-conversion cp.async tf32 GEMM.
// grid (32, 12, 2 n-splits); 256 threads (8 warps: 4m x 2n). 2 CTAs/SM.
// Block tile: M=128, N=32 per matrix x3. Warp tile m32 x n16 x3.
// 3-stage ring, one barrier/chunk, copy issued after the barrier.
// (unchanged from round 11)
// ---------------------------------------------------------------------------
#define XSTR 36
#define WSTR2 40
#define PXW  (128*XSTR)           // 4608 words: X part of a stage
#define PWW  (3*32*WSTR2)         // 3840 words: W part of a stage
#define PSTG (PXW + PWW)          // 8448 words per stage
#define PNC  (DIN/32)             // 24 k-chunks

__global__ __launch_bounds__(256, 2)
void qkv_proj_kernel() {
    extern __shared__ uint32_t psm[];

    const int tid = threadIdx.x;
    const int wid = tid >> 5, lane = tid & 31;
    const int tg = lane >> 2, tig = lane & 3;
    const int wm = wid >> 1, wn = wid & 1;      // 4m x 2n warps
    const int h = blockIdx.y;
    const int ns = blockIdx.z;                  // n-split: cols [ns*32, ns*32+32)
    const int rowblk = blockIdx.x * 128;

    const uint32_t* xr = g_Xr + (size_t)rowblk * DIN;
    const uint32_t* wb = g_Wr + (size_t)h * DIN * DH + ns*32;

    const uint32_t smem_base = (uint32_t)__cvta_generic_to_shared(psm);

    float acc[3][2][2][4];
    #pragma unroll
    for (int m = 0; m < 3; m++)
        #pragma unroll
        for (int i = 0; i < 2; i++)
            #pragma unroll
            for (int j = 0; j < 2; j++)
                #pragma unroll
                for (int r = 0; r < 4; r++) acc[m][i][j][r] = 0.f;

    auto copy_chunk = [&](int kc, int stage) {
        const uint32_t sb = smem_base + stage * (PSTG*4);
        // X: 1024 16B chunks (128 rows x 8)
        #pragma unroll
        for (int u = 0; u < 4; u++) {
            int idx = tid + u*256, r = idx >> 3, c4 = (idx & 7) * 4;
            cpa16(sb + (r*XSTR + c4)*4, xr + (size_t)r*DIN + kc*32 + c4);
        }
        // W: 768 16B chunks (3 mats x 32 k x 8)
        #pragma unroll
        for (int u = 0; u < 3; u++) {
            int k = tid >> 3, n4 = (tid & 7) * 4;
            cpa16(sb + (PXW + u*(32*WSTR2) + k*WSTR2 + n4)*4,
                  wb + (size_t)u*WWRD + (size_t)(kc*32 + k)*DH + n4);
        }
        cpa_commit();
    };

    copy_chunk(0, 0);
    copy_chunk(1, 1);

    for (int kc = 0; kc < PNC; kc++) {
        if (kc + 1 < PNC) cpa_wait<1>(); else cpa_wait<0>();
        __syncthreads();
        if (kc + 2 < PNC) copy_chunk(kc + 2, (kc + 2) % 3);

        const uint32_t* Xs = psm + (kc % 3) * PSTG;
        const uint32_t* Ws = Xs + PXW;

        #pragma unroll
        for (int kk = 0; kk < 4; kk++) {
            const int k0 = kk * 8;
            uint32_t a[2][4];
            #pragma unroll
            for (int ms = 0; ms < 2; ms++) {
                int r0 = wm*32 + ms*16 + tg;
                a[ms][0] = Xs[(r0    )*XSTR + k0 + tig    ];
                a[ms][1] = Xs[(r0 + 8)*XSTR + k0 + tig    ];
                a[ms][2] = Xs[(r0    )*XSTR + k0 + tig + 4];
                a[ms][3] = Xs[(r0 + 8)*XSTR + k0 + tig + 4];
            }
            #pragma unroll
            for (int m = 0; m < 3; m++) {
                #pragma unroll
                for (int j = 0; j < 2; j++) {
                    int n0 = wn*16 + j*8 + tg;
                    uint32_t b0 = Ws[m*(32*WSTR2) + (k0 + tig    )*WSTR2 + n0];
                    uint32_t b1 = Ws[m*(32*WSTR2) + (k0 + tig + 4)*WSTR2 + n0];
                    #pragma unroll
                    for (int ms = 0; ms < 2; ms++)
                        mma_tf32(acc[m][ms][j], a[ms][0], a[ms][1], a[ms][2], a[ms][3], b0, b1);
                }
            }
        }
    }
    __syncthreads();   // all warps finished mma before smem reuse below

    // ------------------- Epilogue -------------------
    const int b = rowblk >> 10;
    const int s0 = rowblk & 1023;
    const size_t base = (((size_t)b*HH + h)*SS);

    // Q: fp32 direct (this CTA's 32 columns)
    #pragma unroll
    for (int ms = 0; ms < 2; ms++) {
        int r0 = s0 + wm*32 + ms*16 + tg;
        #pragma unroll
        for (int j = 0; j < 2; j++) {
            int c0 = ns*32 + wn*16 + j*8 + tig*2;
            #pragma unroll
            for (int half = 0; half < 2; half++) {
                *(float2*)&g_Qf[(base + r0 + half*8)*DH + c0] =
                    make_float2(acc[0][ms][j][half*2], acc[0][ms][j][half*2+1]);
            }
        }
    }

    // K, V: bounce through smem (fp32, local 32 cols, stride 36), emit units.
    float* Ksm = (float*)psm;                 // [128][36]
    float* Vsm = (float*)psm + 128*36;        // [128][36]
    #pragma unroll
    for (int ms = 0; ms < 2; ms++) {
        int rl = wm*32 + ms*16 + tg;
        #pragma unroll
        for (int j = 0; j < 2; j++) {
            int c0 = wn*16 + j*8 + tig*2;     // local column
            #pragma unroll
            for (int half = 0; half < 2; half++) {
                *(float2*)&Ksm[(rl + half*8)*36 + c0] =
                    make_float2(acc[1][ms][j][half*2], acc[1][ms][j][half*2+1]);
                *(float2*)&Vsm[(rl + half*8)*36 + c0] =
                    make_float2(acc[2][ms][j][half*2], acc[2][ms][j][half*2+1]);
            }
        }
    }
    __syncthreads();

    // Kf: this CTA's 2048 8B units (k8 in [ns*4, ns*4+4)), linear stores
    {
        uint32_t* kf = g_Kf + (base + s0)*DH;
        #pragma unroll
        for (int u = 0; u < 8; u++) {
            int idx = tid + u*256;            // 0..2047
            int sl = idx >> 4, unl = idx & 15;
            int k8l = unl >> 2, tgu = unl & 3;
            int cl = k8l*8 + tgu;
            float f0 = Ksm[sl*36 + cl];
            float f1 = Ksm[sl*36 + cl + 4];
            int un = ns*16 + unl;
            *(uint2*)&kf[(size_t)sl*64 + un*2] = make_uint2(f2tf32(f0), f2tf32(f1));
        }
    }
    // Vf: this CTA's 2048 8B units (e in [ns*32, ns*32+32))
    {
        uint32_t* vf = g_Vf + ((size_t)b*HH + h) * (DH*SS);
        #pragma unroll
        for (int u = 0; u < 8; u++) {
            int idx = tid + u*256;            // 0..2047
            int el = idx >> 6, rem = idx & 63;
            int ks8l = rem >> 2, tgu = rem & 3;
            int sl = ks8l*8 + tgu;
            float f0 = Vsm[(sl    )*36 + el];
            float f1 = Vsm[(sl + 4)*36 + el];
            *(uint2*)&vf[(size_t)(ns*32 + el)*1024 + ((s0 >> 3) + ks8l)*8 + tgu*2] =
                make_uint2(f2tf32(f0), f2tf32(f1));
        }
    }
}

// ---------------------------------------------------------------------------
// Kernel 2: tensor-core causal flash attention. Single-tf32 QK^T (Q residual
// dropped — error calibrated from R5->R6 measurement). 2 CTAs/SM, 3-stage
// ring, one barrier per tile. Q pre-scaled by 0.125.
// grid (16, 12, 4); 128 threads (4 warps, warp = 16 q-rows).
// ---------------------------------------------------------------------------
#define STW 8192     // words per stage: K 4096 + V 4096

__global__ __launch_bounds__(128, 2)
void attn_kernel(float* __restrict__ out) {
    extern __shared__ uint32_t smu[];

    const int mt = gridDim.x - 1 - blockIdx.x;
    const int h = blockIdx.y, b = blockIdx.z;
    const int tid = threadIdx.x, wid = tid >> 5, lane = tid & 31;
    const int tg = lane >> 2, tig = lane & 3;
    const int m0 = mt * 64;
    const size_t bh = ((size_t)b*HH + h) * SS;
    const float*    gqf = g_Qf + bh*DH;
    const uint32_t* gkf = g_Kf + bh*DH;
    const uint32_t* gvf = g_Vf + ((size_t)b*HH + h) * (DH*SS);

    const uint32_t smem_base = (uint32_t)__cvta_generic_to_shared(smu);

    // Q fragments: pre-scaled by 0.125 (exact), single tf32 rounding
    uint32_t qb[8][4];
    {
        const int r0 = m0 + wid*16 + tg;
        #pragma unroll
        for (int k = 0; k < 8; k++) {
            qb[k][0] = f2tf32(0.125f * gqf[(size_t)(r0    )*DH + k*8 + tig    ]);
            qb[k][1] = f2tf32(0.125f * gqf[(size_t)(r0 + 8)*DH + k*8 + tig    ]);
            qb[k][2] = f2tf32(0.125f * gqf[(size_t)(r0    )*DH + k*8 + tig + 4]);
            qb[k][3] = f2tf32(0.125f * gqf[(size_t)(r0 + 8)*DH + k*8 + tig + 4]);
        }
    }

    auto copy_tile = [&](int kt, int stage) {
        const uint32_t sb = smem_base + stage * (STW*4);
        #pragma unroll
        for (int u = 0; u < 8; u++) {
            int idx = tid + u*128;
            int s = idx >> 4, cc = idx & 15;
            int ccs = cc ^ ((s & 7) << 1);
            cpa16(sb + s*256 + ccs*16,
                  gkf + ((size_t)(kt*64 + s)*64 + cc*4));
        }
        #pragma unroll
        for (int u = 0; u < 8; u++) {
            int idx = tid + u*128;
            int e = idx >> 4, p = idx & 15;
            int un = 2*p;
            int usw = un ^ ((e & 7) << 2);
            cpa16(sb + 4096*4 + (e*32 + usw)*8,
                  gvf + (size_t)e*1024 + (kt*32 + un)*2);
        }
        cpa_commit();
    };

    float o[8][4];
    #pragma unroll
    for (int j = 0; j < 8; j++)
        #pragma unroll
        for (int i = 0; i < 4; i++) o[j][i] = 0.f;
    float mrow[2] = {-1e30f, -1e30f};
    float lrow[2] = {0.f, 0.f};

    copy_tile(0, 0);
    if (mt >= 1) copy_tile(1, 1);

    for (int kt = 0; kt <= mt; kt++) {
        if (kt + 1 <= mt) cpa_wait<1>(); else cpa_wait<0>();
        __syncthreads();
        if (kt + 2 <= mt) copy_tile(kt + 2, (kt + 2) % 3);

        const uint32_t* Kst = smu + (kt % 3)*STW;
        const uint32_t* Vst = Kst + 4096;

        float c[8][4];
        #pragma unroll
        for (int j = 0; j < 8; j++)
            #pragma unroll
            for (int i = 0; i < 4; i++) c[j][i] = 0.f;

        // ---- S = Q K^T (single tf32 mma per k-step) ----
        #pragma unroll
        for (int k = 0; k < 8; k++) {
            const int un = k*4 + tig;
            const int cc = un >> 1, half = un & 1;
            #pragma unroll
            for (int j = 0; j < 8; j++) {
                const int nr = j*8 + tg;
                int ccs = cc ^ ((nr & 7) << 1);
                uint2 kv = *(const uint2*)&Kst[nr*64 + ccs*4 + half*2];
                mma_tf32(c[j], qb[k][0], qb[k][1], qb[k][2], qb[k][3], kv.x, kv.y);
            }
        }

        if (kt == mt) {       // diagonal tile: causal mask
            const int rl0 = wid*16 + tg, rl1 = rl0 + 8;
            #pragma unroll
            for (int j = 0; j < 8; j++) {
                int c0 = j*8 + 2*tig, c1 = c0 + 1;
                if (c0 > rl0) c[j][0] = -1e30f;
                if (c1 > rl0) c[j][1] = -1e30f;
                if (c0 > rl1) c[j][2] = -1e30f;
                if (c1 > rl1) c[j][3] = -1e30f;
            }
        }

        float alpha[2];
        #pragma unroll
        for (int h2 = 0; h2 < 2; h2++) {
            float mx = -1e30f;
            #pragma unroll
            for (int j = 0; j < 8; j++) {
                mx = fmaxf(mx, c[j][h2*2]);
                mx = fmaxf(mx, c[j][h2*2 + 1]);
            }
            mx = fmaxf(mx, __shfl_xor_sync(0xffffffffu, mx, 1));
            mx = fmaxf(mx, __shfl_xor_sync(0xffffffffu, mx, 2));
            float mnew = fmaxf(mrow[h2], mx);
            float sum = 0.f;
            #pragma unroll
            for (int j = 0; j < 8; j++) {
                float p0 = __expf(c[j][h2*2]     - mnew);
                float p1 = __expf(c[j][h2*2 + 1] - mnew);
                c[j][h2*2]     = p0;
                c[j][h2*2 + 1] = p1;
                sum += p0 + p1;
            }
            sum += __shfl_xor_sync(0xffffffffu, sum, 1);
            sum += __shfl_xor_sync(0xffffffffu, sum, 2);
            alpha[h2] = __expf(mrow[h2] - mnew);
            mrow[h2] = mnew;
            lrow[h2] = lrow[h2]*alpha[h2] + sum;
        }

        #pragma unroll
        for (int j = 0; j < 8; j++) {
            o[j][0] *= alpha[0]; o[j][1] *= alpha[0];
            o[j][2] *= alpha[1]; o[j][3] *= alpha[1];
        }

        const int src0 = (tg << 2) + (tig >> 1);
        const int src1 = src0 + 2;
        const bool odd = (tig & 1);
        #pragma unroll
        for (int k = 0; k < 8; k++) {
            float e0 = __shfl_sync(0xffffffffu, c[k][0], src0);
            float o0 = __shfl_sync(0xffffffffu, c[k][1], src0);
            float e1 = __shfl_sync(0xffffffffu, c[k][2], src0);
            float o1 = __shfl_sync(0xffffffffu, c[k][3], src0);
            float e2 = __shfl_sync(0xffffffffu, c[k][0], src1);
            float o2 = __shfl_sync(0xffffffffu, c[k][1], src1);
            float e3 = __shfl_sync(0xffffffffu, c[k][2], src1);
            float o3 = __shfl_sync(0xffffffffu, c[k][3], src1);
            uint32_t a0 = f2tf32(odd ? o0 : e0);
            uint32_t a1 = f2tf32(odd ? o1 : e1);
            uint32_t a2 = f2tf32(odd ? o2 : e2);
            uint32_t a3 = f2tf32(odd ? o3 : e3);

            const int usw = (k*4 + tig) ^ (tg << 2);
            #pragma unroll
            for (int jn = 0; jn < 8; jn++) {
                const int e = jn*8 + tg;
                uint2 vf = *(const uint2*)&Vst[(e*32 + usw)*2];
                mma_tf32(o[jn], a0, a1, a2, a3, vf.x, vf.y);
            }
        }
        // no trailing barrier: stage reuse sealed by barrier at iter kt+2.
    }

    const float inv0 = 1.f / lrow[0], inv1 = 1.f / lrow[1];
    const int r0 = m0 + wid*16 + tg;
    #pragma unroll
    for (int j = 0; j < 8; j++) {
        int col = h*DH + j*8 + 2*tig;
        *(float2*)&out[((size_t)b*SS + r0    )*(HH*DH) + col] =
            make_float2(o[j][0]*inv0, o[j][1]*inv0);
        *(float2*)&out[((size_t)b*SS + r0 + 8)*(HH*DH) + col] =
            make_float2(o[j][2]*inv1, o[j][3]*inv1);
    }
}

// ---------------------------------------------------------------------------
extern "C" void kernel_launch(void* const* d_in, const int* in_sizes, int n_in,
                              void* d_out, int out_size) {
    const float* x  = (const float*)d_in[0];
    const float* Wq = (const float*)d_in[1];
    const float* Wk = (const float*)d_in[2];
    const float* Wv = (const float*)d_in[3];
    float* out = (float*)d_out;

    round_kernel<<<1184, 256>>>((const uint4*)x, (const uint4*)Wq,
                                (const uint4*)Wk, (const uint4*)Wv);

    const int proj_smem = 3 * PSTG * (int)sizeof(uint32_t);        // 101,376 B
    cudaFuncSetAttribute(qkv_proj_kernel, cudaFuncAttributeMaxDynamicSharedMemorySize,
                         proj_smem);
    qkv_proj_kernel<<<dim3((BB*SS)/128, HH, 2), 256, proj_smem>>>();

    const int attn_smem = 3 * STW * (int)sizeof(uint32_t);         // 98,304 B
    cudaFuncSetAttribute(attn_kernel, cudaFuncAttributeMaxDynamicSharedMemorySize,
                         attn_smem);
    attn_kernel<<<dim3(SS/64, HH, BB), 128, attn_smem>>>(out);
}

// round 13
// speedup vs baseline: 1.6835x; 1.3728x over previous
#include <cuda_runtime.h>
#include <cuda_fp16.h>
#include <cstdint>

// Problem constants
#define BB   4
#define SS   1024
#define DIN  768
#define HH   12
#define DH   64
#define WWRD (HH*DIN*DH)

// Scratch (device globals; no allocs allowed). fp16 pair-unit layouts:
// unit(row, kk, tig) = { f16x2(v[16kk+2tig], v[16kk+2tig+1]),
//                        f16x2(v[16kk+8+2tig], v[16kk+9+2tig]) }   (8 bytes)
__device__ __align__(16) uint32_t g_Xf16[BB*SS*DIN/2];        // [row][kk48][tig4]
__device__ __align__(16) uint32_t g_Wf16[3*WWRD/2];           // [(m,h)][kc24][n64][u8]
__device__ __align__(16) float    g_Qf  [BB*HH*SS*DH];        // fp32 [b,h,s,e]
__device__ __align__(16) uint32_t g_Kf16[(size_t)BB*HH*SS*DH/2]; // [s][u16][2w] per (b,h)
__device__ __align__(16) uint32_t g_Vf16[(size_t)BB*HH*DH*SS/2]; // [e][K0*4+tig][2w]

// ---------------------------------------------------------------------------
// helpers
// ---------------------------------------------------------------------------
__device__ __forceinline__ uint32_t pkh(float a, float b) {
    __half2 h = __floats2half2_rn(a, b);
    return *reinterpret_cast<uint32_t*>(&h);
}

__device__ __forceinline__ void mma_f16(float c[4],
                                        uint32_t a0, uint32_t a1, uint32_t a2, uint32_t a3,
                                        uint32_t b0, uint32_t b1) {
    asm volatile(
        "mma.sync.aligned.m16n8k16.row.col.f32.f16.f16.f32 "
        "{%0,%1,%2,%3}, {%4,%5,%6,%7}, {%8,%9}, {%0,%1,%2,%3};"
        : "+f"(c[0]), "+f"(c[1]), "+f"(c[2]), "+f"(c[3])
        : "r"(a0), "r"(a1), "r"(a2), "r"(a3), "r"(b0), "r"(b1));
}

__device__ __forceinline__ void cpa16(uint32_t smem_addr, const void* gptr) {
    asm volatile("cp.async.cg.shared.global [%0], [%1], 16;"
                 :: "r"(smem_addr), "l"(gptr));
}
__device__ __forceinline__ void cpa_commit() {
    asm volatile("cp.async.commit_group;");
}
template <int N>
__device__ __forceinline__ void cpa_wait() {
    asm volatile("cp.async.wait_group %0;" :: "n"(N));
}

// ---------------------------------------------------------------------------
// Kernel 0a: x fp32 -> fp16 pair units. One (row, kk16) per thread.
// ---------------------------------------------------------------------------
__global__ __launch_bounds__(256)
void prep_x(const float* __restrict__ x) {
    int idx = blockIdx.x*256 + threadIdx.x;      // 0..196607
    int row = idx / 48, kk = idx % 48;
    const float4* src = (const float4*)(x + (size_t)row*DIN + kk*16);
    float4 v0 = src[0], v1 = src[1], v2 = src[2], v3 = src[3];
    float f[16] = {v0.x,v0.y,v0.z,v0.w, v1.x,v1.y,v1.z,v1.w,
                   v2.x,v2.y,v2.z,v2.w, v3.x,v3.y,v3.z,v3.w};
    uint32_t w[8];
    #pragma unroll
    for (int tg = 0; tg < 4; tg++) {
        w[tg*2]   = pkh(f[2*tg],     f[2*tg + 1]);
        w[tg*2+1] = pkh(f[8 + 2*tg], f[9 + 2*tg]);
    }
    uint4* dst = (uint4*)&g_Xf16[(size_t)row*384 + kk*8];
    dst[0] = *(uint4*)&w[0];
    dst[1] = *(uint4*)&w[4];
}

// ---------------------------------------------------------------------------
// Kernel 0b: W [h][k][n] fp32 -> fp16 pair units [(m,h)][kc][n][u8].
// grid (24 kc, 12 h, 3 m), 256 threads, smem bounce.
// ---------------------------------------------------------------------------
__global__ __launch_bounds__(256)
void prep_w(const float* __restrict__ Wq, const float* __restrict__ Wk,
            const float* __restrict__ Wv) {
    __shared__ float sm[32*65];
    const int kc = blockIdx.x, h = blockIdx.y, m = blockIdx.z;
    const int tid = threadIdx.x;
    const float* src = ((m == 0) ? Wq : (m == 1) ? Wk : Wv)
                       + (size_t)h*DIN*DH + (size_t)kc*32*DH;
    #pragma unroll
    for (int it = 0; it < 8; it++) {
        int idx = tid + it*256;            // 0..2047
        int k = idx >> 6, n = idx & 63;
        sm[k*65 + n] = src[k*64 + n];
    }
    __syncthreads();
    uint32_t* dst = g_Wf16 + ((size_t)((m*HH + h)*24 + kc))*1024;  // 64n x 16w
    #pragma unroll
    for (int it = 0; it < 2; it++) {
        int idx = tid + it*256;            // 0..511
        int n = idx >> 3, u = idx & 7;
        int kkl = u >> 2, tg = u & 3;
        int c0 = kkl*16 + 2*tg;
        uint2 val = make_uint2(pkh(sm[(c0    )*65 + n], sm[(c0 + 1)*65 + n]),
                               pkh(sm[(c0 + 8)*65 + n], sm[(c0 + 9)*65 + n]));
        *(uint2*)&dst[n*16 + u*2] = val;
    }
}

// ---------------------------------------------------------------------------
// Kernel 1: fused QKV projection, fp16 m16n8k16 cp.async GEMM.
// grid (32, 12, 2 n-splits); 256 threads (8 warps: 4m x 2n). 2 CTAs/SM.
// Block tile M=128, N=32 per matrix x3. 3-stage ring, 1 barrier/chunk(K=32).
// ---------------------------------------------------------------------------
#define PXW  (128*20)             // 2560 words: X part (row stride 20, 4 chunks + pad)
#define PWW  (3*32*20)            // 1920 words: W part
#define PSTG (PXW + PWW)          // 4480 words per stage
#define PNC  (DIN/32)             // 24 chunks of K=32

__global__ __launch_bounds__(256, 2)
void qkv_proj_kernel() {
    extern __shared__ uint32_t psm[];

    const int tid = threadIdx.x;
    const int wid = tid >> 5, lane = tid & 31;
    const int tg = lane >> 2, tig = lane & 3;
    const int wm = wid >> 1, wn = wid & 1;      // 4m x 2n warps
    const int h = blockIdx.y;
    const int ns = blockIdx.z;
    const int rowblk = blockIdx.x * 128;

    const uint32_t smem_base = (uint32_t)__cvta_generic_to_shared(psm);

    float acc[3][2][2][4];
    #pragma unroll
    for (int m = 0; m < 3; m++)
        #pragma unroll
        for (int i = 0; i < 2; i++)
            #pragma unroll
            for (int j = 0; j < 2; j++)
                #pragma unroll
                for (int r = 0; r < 4; r++) acc[m][i][j][r] = 0.f;

    auto copy_chunk = [&](int kc, int stage) {
        const uint32_t sb = smem_base + stage * (PSTG*4);
        // 896 16B chunks: 512 X + 384 W
        #pragma unroll
        for (int u = 0; u < 4; u++) {
            int idx = tid + u*256;
            if (idx < 512) {
                int r = idx >> 2, cc = idx & 3;
                cpa16(sb + (r*20 + cc*4)*4,
                      g_Xf16 + (size_t)(rowblk + r)*384 + kc*16 + cc*4);
            } else if (idx < 896) {
                int widx = idx - 512;
                int m = widx >> 7, rem = widx & 127;
                int n = rem >> 2, cc = rem & 3;
                cpa16(sb + (PXW + m*640 + n*20 + cc*4)*4,
                      g_Wf16 + ((size_t)((m*HH + h)*24 + kc))*1024
                             + (size_t)(ns*32 + n)*16 + cc*4);
            }
        }
        cpa_commit();
    };

    copy_chunk(0, 0);
    copy_chunk(1, 1);

    for (int kc = 0; kc < PNC; kc++) {
        if (kc + 1 < PNC) cpa_wait<1>(); else cpa_wait<0>();
        __syncthreads();
        if (kc + 2 < PNC) copy_chunk(kc + 2, (kc + 2) % 3);

        const uint32_t* Xs = psm + (kc % 3) * PSTG;
        const uint32_t* Ws = Xs + PXW;

        #pragma unroll
        for (int ks = 0; ks < 2; ks++) {            // 2 k16 steps per chunk
            const int u = ks*4 + tig;
            uint32_t a[2][4];
            #pragma unroll
            for (int ms = 0; ms < 2; ms++) {
                int r0 = wm*32 + ms*16 + tg;
                uint2 lo = *(const uint2*)&Xs[(r0    )*20 + u*2];
                uint2 hi = *(const uint2*)&Xs[(r0 + 8)*20 + u*2];
                a[ms][0] = lo.x; a[ms][1] = hi.x; a[ms][2] = lo.y; a[ms][3] = hi.y;
            }
            #pragma unroll
            for (int m = 0; m < 3; m++) {
                #pragma unroll
                for (int j = 0; j < 2; j++) {
                    int n0 = wn*16 + j*8 + tg;
                    uint2 bv = *(const uint2*)&Ws[m*640 + n0*20 + u*2];
                    #pragma unroll
                    for (int ms = 0; ms < 2; ms++)
                        mma_f16(acc[m][ms][j], a[ms][0], a[ms][1], a[ms][2], a[ms][3],
                                bv.x, bv.y);
                }
            }
        }
    }
    __syncthreads();   // all mma done before smem reuse

    // ------------------- Epilogue -------------------
    const int b = rowblk >> 10;
    const int s0 = rowblk & 1023;
    const size_t base = (((size_t)b*HH + h)*SS);

    // Q: fp32 direct (this CTA's 32 columns)
    #pragma unroll
    for (int ms = 0; ms < 2; ms++) {
        int r0 = s0 + wm*32 + ms*16 + tg;
        #pragma unroll
        for (int j = 0; j < 2; j++) {
            int c0 = ns*32 + wn*16 + j*8 + tig*2;
            #pragma unroll
            for (int half = 0; half < 2; half++) {
                *(float2*)&g_Qf[(base + r0 + half*8)*DH + c0] =
                    make_float2(acc[0][ms][j][half*2], acc[0][ms][j][half*2+1]);
            }
        }
    }

    // K, V: bounce through smem (fp32, stride 36), emit fp16 pair units.
    float* Ksm = (float*)psm;                 // [128][36]
    float* Vsm = (float*)psm + 128*36;        // [128][36]
    #pragma unroll
    for (int ms = 0; ms < 2; ms++) {
        int rl = wm*32 + ms*16 + tg;
        #pragma unroll
        for (int j = 0; j < 2; j++) {
            int c0 = wn*16 + j*8 + tig*2;     // local column
            #pragma unroll
            for (int half = 0; half < 2; half++) {
                *(float2*)&Ksm[(rl + half*8)*36 + c0] =
                    make_float2(acc[1][ms][j][half*2], acc[1][ms][j][half*2+1]);
                *(float2*)&Vsm[(rl + half*8)*36 + c0] =
                    make_float2(acc[2][ms][j][half*2], acc[2][ms][j][half*2+1]);
            }
        }
    }
    __syncthreads();

    // Kf16: per s-row, local kk' in {0,1} (global kk = ns*2+kk'), 4 tig units.
    {
        uint32_t* kf = g_Kf16 + (base + s0)*32;
        #pragma unroll
        for (int u = 0; u < 4; u++) {
            int idx = tid + u*256;            // 0..1023
            int sl = idx >> 3, ul = idx & 7;
            int kkl = ul >> 2, tgu = ul & 3;
            int c0 = kkl*16 + 2*tgu;
            uint2 val = make_uint2(pkh(Ksm[sl*36 + c0    ], Ksm[sl*36 + c0 + 1]),
                                   pkh(Ksm[sl*36 + c0 + 8], Ksm[sl*36 + c0 + 9]));
            int kk = ns*2 + kkl;
            *(uint2*)&kf[(size_t)sl*32 + (kk*4 + tgu)*2] = val;
        }
    }
    // Vf16: per local e, K0 local in [0,8), 4 tig units (pairs over s).
    {
        uint32_t* vf = g_Vf16 + ((size_t)b*HH + h) * (DH*SS/2);
        #pragma unroll
        for (int u = 0; u < 4; u++) {
            int idx = tid + u*256;            // 0..1023
            int el = idx >> 5, rem = idx & 31;
            int K0l = rem >> 2, tgu = rem & 3;
            int sl0 = K0l*16 + 2*tgu;
            uint2 val = make_uint2(pkh(Vsm[(sl0    )*36 + el], Vsm[(sl0 + 1)*36 + el]),
                                   pkh(Vsm[(sl0 + 8)*36 + el], Vsm[(sl0 + 9)*36 + el]));
            int e = ns*32 + el;
            *(uint2*)&vf[(size_t)e*512 + ((s0 >> 4) + K0l)*8 + tgu*2] = val;
        }
    }
}

// ---------------------------------------------------------------------------
// Kernel 2: fp16 tensor-core causal flash attention. m16n8k16 for QK and PV;
// P transposes into the A-fragment for free (C-frag pairing == A-frag pairing).
// grid (16, 12, 4); 128 threads; 3-stage ring, 1 barrier/tile; 2 CTAs/SM.
// ---------------------------------------------------------------------------
#define STW 4096     // words per stage: K 2048 + V 2048 (16KB)

__global__ __launch_bounds__(128, 2)
void attn_kernel(float* __restrict__ out) {
    extern __shared__ uint32_t smu[];

    const int mt = gridDim.x - 1 - blockIdx.x;
    const int h = blockIdx.y, b = blockIdx.z;
    const int tid = threadIdx.x, wid = tid >> 5, lane = tid & 31;
    const int tg = lane >> 2, tig = lane & 3;
    const int m0 = mt * 64;
    const size_t bh = ((size_t)b*HH + h) * SS;
    const float*    gqf = g_Qf + bh*DH;
    const uint32_t* gkf = g_Kf16 + bh*32;
    const uint32_t* gvf = g_Vf16 + ((size_t)b*HH + h) * (DH*SS/2);

    const uint32_t smem_base = (uint32_t)__cvta_generic_to_shared(smu);

    // Q fragments: fp32 load, scale by 0.125, pack to f16x2 pairs.
    uint32_t qa[4][4];
    {
        const int r0 = m0 + wid*16 + tg;
        #pragma unroll
        for (int kk = 0; kk < 4; kk++) {
            float2 lo0 = *(const float2*)&gqf[(size_t)(r0    )*DH + kk*16 + 2*tig];
            float2 lo1 = *(const float2*)&gqf[(size_t)(r0 + 8)*DH + kk*16 + 2*tig];
            float2 hi0 = *(const float2*)&gqf[(size_t)(r0    )*DH + kk*16 + 8 + 2*tig];
            float2 hi1 = *(const float2*)&gqf[(size_t)(r0 + 8)*DH + kk*16 + 8 + 2*tig];
            qa[kk][0] = pkh(0.125f*lo0.x, 0.125f*lo0.y);
            qa[kk][1] = pkh(0.125f*lo1.x, 0.125f*lo1.y);
            qa[kk][2] = pkh(0.125f*hi0.x, 0.125f*hi0.y);
            qa[kk][3] = pkh(0.125f*hi1.x, 0.125f*hi1.y);
        }
    }

    auto copy_tile = [&](int kt, int stage) {
        const uint32_t sb = smem_base + stage * (STW*4);
        // K: 512 16B chunks (64 rows x 8)
        #pragma unroll
        for (int u = 0; u < 4; u++) {
            int idx = tid + u*128;
            int n = idx >> 3, cc = idx & 7;
            int ccs = cc ^ (n & 7);
            cpa16(sb + n*128 + ccs*16,
                  gkf + ((size_t)(kt*64 + n)*32 + cc*4));
        }
        // V: 512 16B chunks (64 e-rows x 8)
        #pragma unroll
        for (int u = 0; u < 4; u++) {
            int idx = tid + u*128;
            int e = idx >> 3, cc = idx & 7;
            int ccs = cc ^ (e & 7);
            cpa16(sb + 2048*4 + e*128 + ccs*16,
                  gvf + ((size_t)e*512 + kt*32 + cc*4));
        }
        cpa_commit();
    };

    float o[8][4];
    #pragma unroll
    for (int j = 0; j < 8; j++)
        #pragma unroll
        for (int i = 0; i < 4; i++) o[j][i] = 0.f;
    float mrow[2] = {-1e30f, -1e30f};
    float lrow[2] = {0.f, 0.f};

    copy_tile(0, 0);
    if (mt >= 1) copy_tile(1, 1);

    for (int kt = 0; kt <= mt; kt++) {
        if (kt + 1 <= mt) cpa_wait<1>(); else cpa_wait<0>();
        __syncthreads();
        if (kt + 2 <= mt) copy_tile(kt + 2, (kt + 2) % 3);

        const uint32_t* Kst = smu + (kt % 3)*STW;
        const uint32_t* Vst = Kst + 2048;

        float c[8][4];
        #pragma unroll
        for (int j = 0; j < 8; j++)
            #pragma unroll
            for (int i = 0; i < 4; i++) c[j][i] = 0.f;

        // ---- S = Q K^T : 4 k16-steps x 8 n-blocks ----
        #pragma unroll
        for (int kk = 0; kk < 4; kk++) {
            const int u = kk*4 + tig;
            const int cc = u >> 1, half = u & 1;
            #pragma unroll
            for (int j = 0; j < 8; j++) {
                const int nr = j*8 + tg;
                uint2 kv = *(const uint2*)&Kst[nr*32 + (cc ^ (nr & 7))*4 + half*2];
                mma_f16(c[j], qa[kk][0], qa[kk][1], qa[kk][2], qa[kk][3], kv.x, kv.y);
            }
        }

        if (kt == mt) {       // diagonal tile: causal mask
            const int rl0 = wid*16 + tg, rl1 = rl0 + 8;
            #pragma unroll
            for (int j = 0; j < 8; j++) {
                int c0 = j*8 + 2*tig, c1 = c0 + 1;
                if (c0 > rl0) c[j][0] = -1e30f;
                if (c1 > rl0) c[j][1] = -1e30f;
                if (c0 > rl1) c[j][2] = -1e30f;
                if (c1 > rl1) c[j][3] = -1e30f;
            }
        }

        float alpha[2];
        #pragma unroll
        for (int h2 = 0; h2 < 2; h2++) {
            float mx = -1e30f;
            #pragma unroll
            for (int j = 0; j < 8; j++) {
                mx = fmaxf(mx, c[j][h2*2]);
                mx = fmaxf(mx, c[j][h2*2 + 1]);
            }
            mx = fmaxf(mx, __shfl_xor_sync(0xffffffffu, mx, 1));
            mx = fmaxf(mx, __shfl_xor_sync(0xffffffffu, mx, 2));
            float mnew = fmaxf(mrow[h2], mx);
            float sum = 0.f;
            #pragma unroll
            for (int j = 0; j < 8; j++) {
                float p0 = __expf(c[j][h2*2]     - mnew);
                float p1 = __expf(c[j][h2*2 + 1] - mnew);
                c[j][h2*2]     = p0;
                c[j][h2*2 + 1] = p1;
                sum += p0 + p1;
            }
            sum += __shfl_xor_sync(0xffffffffu, sum, 1);
            sum += __shfl_xor_sync(0xffffffffu, sum, 2);
            alpha[h2] = __expf(mrow[h2] - mnew);
            mrow[h2] = mnew;
            lrow[h2] = lrow[h2]*alpha[h2] + sum;
        }

        #pragma unroll
        for (int j = 0; j < 8; j++) {
            o[j][0] *= alpha[0]; o[j][1] *= alpha[0];
            o[j][2] *= alpha[1]; o[j][3] *= alpha[1];
        }

        // ---- O += P V : C-frag pairs ARE the A-frag pairs (no shuffles) ----
        #pragma unroll
        for (int K0 = 0; K0 < 4; K0++) {
            uint32_t a0 = pkh(c[2*K0    ][0], c[2*K0    ][1]);
            uint32_t a1 = pkh(c[2*K0    ][2], c[2*K0    ][3]);
            uint32_t a2 = pkh(c[2*K0 + 1][0], c[2*K0 + 1][1]);
            uint32_t a3 = pkh(c[2*K0 + 1][2], c[2*K0 + 1][3]);
            const int u = K0*4 + tig;
            const int cc = u >> 1, half = u & 1;
            #pragma unroll
            for (int jn = 0; jn < 8; jn++) {
                const int e = jn*8 + tg;
                uint2 vv = *(const uint2*)&Vst[e*32 + (cc ^ (e & 7))*4 + half*2];
                mma_f16(o[jn], a0, a1, a2, a3, vv.x, vv.y);
            }
        }
        // stage reuse sealed by barrier at iteration kt+2
    }

    const float inv0 = 1.f / lrow[0], inv1 = 1.f / lrow[1];
    const int r0 = m0 + wid*16 + tg;
    #pragma unroll
    for (int j = 0; j < 8; j++) {
        int col = h*DH + j*8 + 2*tig;
        *(float2*)&out[((size_t)b*SS + r0    )*(HH*DH) + col] =
            make_float2(o[j][0]*inv0, o[j][1]*inv0);
        *(float2*)&out[((size_t)b*SS + r0 + 8)*(HH*DH) + col] =
            make_float2(o[j][2]*inv1, o[j][3]*inv1);
    }
}

// ---------------------------------------------------------------------------
extern "C" void kernel_launch(void* const* d_in, const int* in_sizes, int n_in,
                              void* d_out, int out_size) {
    const float* x  = (const float*)d_in[0];
    const float* Wq = (const float*)d_in[1];
    const float* Wk = (const float*)d_in[2];
    const float* Wv = (const float*)d_in[3];
    float* out = (float*)d_out;

    prep_x<<<768, 256>>>(x);
    prep_w<<<dim3(24, HH, 3), 256>>>(Wq, Wk, Wv);

    const int proj_smem = 3 * PSTG * (int)sizeof(uint32_t);        // 53,760 B
    cudaFuncSetAttribute(qkv_proj_kernel, cudaFuncAttributeMaxDynamicSharedMemorySize,
                         proj_smem);
    qkv_proj_kernel<<<dim3((BB*SS)/128, HH, 2), 256, proj_smem>>>();

    const int attn_smem = 3 * STW * (int)sizeof(uint32_t);         // 49,152 B
    cudaFuncSetAttribute(attn_kernel, cudaFuncAttributeMaxDynamicSharedMemorySize,
                         attn_smem);
    attn_kernel<<<dim3(SS/64, HH, BB), 128, attn_smem>>>(out);
}